// round 2
// baseline (speedup 1.0000x reference)
#include <cuda_runtime.h>
#include <math.h>

// Problem constants
#define B_    4
#define NH    12
#define BH    48            // B_*NH
#define S_    1024
#define HD    64
#define HH    32
#define WW    32
#define C_    768
#define C3    2304
#define SCALE 0.125f        // 64^-0.5

// ---------------- scratch (device globals: allocation-free rule) ------------
__device__ float g_q[BH * S_ * HD];          // 12.6 MB
__device__ float g_k[BH * S_ * HD];
__device__ float g_v[BH * S_ * HD];
__device__ float g_relh[BH * S_ * HH];       // 6.3 MB
__device__ float g_relw[BH * S_ * WW];
__device__ float g_scores[(size_t)BH * S_ * S_];  // 201 MB
__device__ float g_att[BH * S_ * HD];

// Tile params: BM=BN=64, BK=16, 256 threads, 4x4 micro-tile per thread.
// Shared stride 68 (== 4 mod 32): <=2-way STS conflicts, 16B-aligned rows.
#define TS 68

// ---------------------------------------------------------------------------
// 1) qkv = x @ Wqkv, scattered into per-head q/k/v
//    A: x (4096 x 768), B: Wqkv (768 x 2304)
// ---------------------------------------------------------------------------
__global__ __launch_bounds__(256) void k_qkv(const float* __restrict__ X,
                                             const float* __restrict__ W) {
    __shared__ float As[16][TS];
    __shared__ float Bs[16][TS];
    const int colBlock = blockIdx.x * 64;
    const int rowBlock = blockIdx.y * 64;
    const int tid = threadIdx.x;
    const int tx = tid & 15, ty = tid >> 4;
    float acc[4][4] = {};

    for (int kt = 0; kt < C_; kt += 16) {
#pragma unroll
        for (int i = 0; i < 4; i++) {           // A tile: 64 rows x 16 k
            int idx = tid + i * 256;
            int r = idx >> 4, c = idx & 15;
            As[c][r] = X[(size_t)(rowBlock + r) * C_ + kt + c];
        }
#pragma unroll
        for (int i = 0; i < 4; i++) {           // B tile: 16 k x 64 cols
            int idx = tid + i * 256;
            int r = idx >> 6, c = idx & 63;
            Bs[r][c] = W[(size_t)(kt + r) * C3 + colBlock + c];
        }
        __syncthreads();
#pragma unroll
        for (int kk = 0; kk < 16; kk++) {
            float4 a4 = *(const float4*)&As[kk][ty * 4];
            float4 b4 = *(const float4*)&Bs[kk][tx * 4];
            float av[4] = {a4.x, a4.y, a4.z, a4.w};
            float bv[4] = {b4.x, b4.y, b4.z, b4.w};
#pragma unroll
            for (int i = 0; i < 4; i++)
#pragma unroll
                for (int j = 0; j < 4; j++) acc[i][j] += av[i] * bv[j];
        }
        __syncthreads();
    }
    // scatter: col -> (part, head, d); row -> (b, s)
#pragma unroll
    for (int i = 0; i < 4; i++) {
        int row = rowBlock + ty * 4 + i;
        int b = row >> 10, s = row & 1023;
#pragma unroll
        for (int j = 0; j < 4; j++) {
            int col = colBlock + tx * 4 + j;
            int part = col / C_;
            int rem = col - part * C_;
            int head = rem >> 6, d = rem & 63;
            float* dst = (part == 0) ? g_q : (part == 1) ? g_k : g_v;
            dst[(((size_t)(b * NH + head)) * S_ + s) * HD + d] = acc[i][j];
        }
    }
}

// ---------------------------------------------------------------------------
// 2) rel_h[bh, h*32+w, kh] = sum_c q[bh, h*32+w, c] * rel_pos_h[h-kh+31, c]
//    one block per (bh, h)
// ---------------------------------------------------------------------------
__global__ __launch_bounds__(256) void k_relh(const float* __restrict__ RH) {
    const int h = blockIdx.x, bh = blockIdx.y;
    __shared__ float Qs[32][HD + 1];
    __shared__ float Rs[32][HD + 1];
    const int tid = threadIdx.x;
#pragma unroll
    for (int i = 0; i < 8; i++) {
        int idx = tid + i * 256;                 // 2048 elems
        int r = idx >> 6, c = idx & 63;
        Qs[r][c] = g_q[((size_t)bh * S_ + h * 32 + r) * HD + c];
        Rs[r][c] = RH[(h - r + 31) * HD + c];    // r plays role of kh
    }
    __syncthreads();
    for (int e = tid; e < 1024; e += 256) {
        int w = e >> 5, kh = e & 31;
        float acc = 0.f;
#pragma unroll
        for (int c = 0; c < HD; c++) acc += Qs[w][c] * Rs[kh][c];
        g_relh[((size_t)bh * S_ + h * 32 + w) * 32 + kh] = acc;
    }
}

// ---------------------------------------------------------------------------
// 3) rel_w[bh, h*32+w, kw] = sum_c q[bh, h*32+w, c] * rel_pos_w[w-kw+31, c]
//    one block per (bh, w)
// ---------------------------------------------------------------------------
__global__ __launch_bounds__(256) void k_relw(const float* __restrict__ RW) {
    const int w = blockIdx.x, bh = blockIdx.y;
    __shared__ float Qs[32][HD + 1];
    __shared__ float Rs[32][HD + 1];
    const int tid = threadIdx.x;
#pragma unroll
    for (int i = 0; i < 8; i++) {
        int idx = tid + i * 256;
        int r = idx >> 6, c = idx & 63;
        Qs[r][c] = g_q[((size_t)bh * S_ + r * 32 + w) * HD + c];  // r = h
        Rs[r][c] = RW[(w - r + 31) * HD + c];    // r plays role of kw
    }
    __syncthreads();
    for (int e = tid; e < 1024; e += 256) {
        int hh = e >> 5, kw = e & 31;
        float acc = 0.f;
#pragma unroll
        for (int c = 0; c < HD; c++) acc += Qs[hh][c] * Rs[kw][c];
        g_relw[((size_t)bh * S_ + hh * 32 + w) * 32 + kw] = acc;
    }
}

// ---------------------------------------------------------------------------
// 4) scores[bh] = SCALE * q[bh] @ k[bh]^T + bias   (1024x1024, K=64)
// ---------------------------------------------------------------------------
__global__ __launch_bounds__(256) void k_scores() {
    const int bh = blockIdx.z;
    const int colBlock = blockIdx.x * 64;
    const int rowBlock = blockIdx.y * 64;
    const float* __restrict__ Q = g_q + (size_t)bh * S_ * HD;
    const float* __restrict__ K = g_k + (size_t)bh * S_ * HD;
    __shared__ float As[16][TS];
    __shared__ float Bs[16][TS];
    const int tid = threadIdx.x;
    const int tx = tid & 15, ty = tid >> 4;
    float acc[4][4] = {};

    for (int kt = 0; kt < HD; kt += 16) {
#pragma unroll
        for (int i = 0; i < 4; i++) {           // Q tile (transposed store)
            int idx = tid + i * 256;
            int r = idx >> 4, c = idx & 15;
            As[c][r] = Q[(size_t)(rowBlock + r) * HD + kt + c];
        }
#pragma unroll
        for (int i = 0; i < 4; i++) {           // K tile (transposed store): Bs[k][n]
            int idx = tid + i * 256;
            int n = idx >> 4, r = idx & 15;
            Bs[r][n] = K[(size_t)(colBlock + n) * HD + kt + r];
        }
        __syncthreads();
#pragma unroll
        for (int kk = 0; kk < 16; kk++) {
            float4 a4 = *(const float4*)&As[kk][ty * 4];
            float4 b4 = *(const float4*)&Bs[kk][tx * 4];
            float av[4] = {a4.x, a4.y, a4.z, a4.w};
            float bv[4] = {b4.x, b4.y, b4.z, b4.w};
#pragma unroll
            for (int i = 0; i < 4; i++)
#pragma unroll
                for (int j = 0; j < 4; j++) acc[i][j] += av[i] * bv[j];
        }
        __syncthreads();
    }
    float* Srow = g_scores + (size_t)bh * S_ * S_;
#pragma unroll
    for (int i = 0; i < 4; i++) {
        int qs = rowBlock + ty * 4 + i;
        const float* rh = g_relh + ((size_t)bh * S_ + qs) * 32;
        const float* rw = g_relw + ((size_t)bh * S_ + qs) * 32;
#pragma unroll
        for (int j = 0; j < 4; j++) {
            int ks = colBlock + tx * 4 + j;
            float bias = rh[ks >> 5] + rw[ks & 31];
            Srow[(size_t)qs * S_ + ks] = SCALE * acc[i][j] + bias;
        }
    }
}

// ---------------------------------------------------------------------------
// 5) row softmax over 1024 elems, one block per row
// ---------------------------------------------------------------------------
__global__ __launch_bounds__(256) void k_softmax() {
    const size_t row = blockIdx.x;
    float* p = g_scores + row * S_;
    const int tid = threadIdx.x;
    __shared__ float red[256];

    float v[4];
    float m = -1e30f;
#pragma unroll
    for (int i = 0; i < 4; i++) { v[i] = p[tid + i * 256]; m = fmaxf(m, v[i]); }
    red[tid] = m;
    __syncthreads();
    for (int s = 128; s > 0; s >>= 1) {
        if (tid < s) red[tid] = fmaxf(red[tid], red[tid + s]);
        __syncthreads();
    }
    m = red[0];
    __syncthreads();

    float sum = 0.f;
#pragma unroll
    for (int i = 0; i < 4; i++) { v[i] = __expf(v[i] - m); sum += v[i]; }
    red[tid] = sum;
    __syncthreads();
    for (int s = 128; s > 0; s >>= 1) {
        if (tid < s) red[tid] += red[tid + s];
        __syncthreads();
    }
    float inv = 1.f / red[0];
#pragma unroll
    for (int i = 0; i < 4; i++) p[tid + i * 256] = v[i] * inv;
}

// ---------------------------------------------------------------------------
// 6) att[bh] = softmax(scores)[bh] @ v[bh]   (1024x64, K=1024)
// ---------------------------------------------------------------------------
__global__ __launch_bounds__(256) void k_av() {
    const int bh = blockIdx.z;
    const int rowBlock = blockIdx.y * 64;
    const float* __restrict__ A = g_scores + (size_t)bh * S_ * S_;
    const float* __restrict__ V = g_v + (size_t)bh * S_ * HD;
    __shared__ float As[16][TS];
    __shared__ float Bs[16][TS];
    const int tid = threadIdx.x;
    const int tx = tid & 15, ty = tid >> 4;
    float acc[4][4] = {};

    for (int kt = 0; kt < S_; kt += 16) {
#pragma unroll
        for (int i = 0; i < 4; i++) {
            int idx = tid + i * 256;
            int r = idx >> 4, c = idx & 15;
            As[c][r] = A[(size_t)(rowBlock + r) * S_ + kt + c];
        }
#pragma unroll
        for (int i = 0; i < 4; i++) {
            int idx = tid + i * 256;
            int r = idx >> 6, c = idx & 63;
            Bs[r][c] = V[(size_t)(kt + r) * HD + c];
        }
        __syncthreads();
#pragma unroll
        for (int kk = 0; kk < 16; kk++) {
            float4 a4 = *(const float4*)&As[kk][ty * 4];
            float4 b4 = *(const float4*)&Bs[kk][tx * 4];
            float av[4] = {a4.x, a4.y, a4.z, a4.w};
            float bv[4] = {b4.x, b4.y, b4.z, b4.w};
#pragma unroll
            for (int i = 0; i < 4; i++)
#pragma unroll
                for (int j = 0; j < 4; j++) acc[i][j] += av[i] * bv[j];
        }
        __syncthreads();
    }
    float* O = g_att + (size_t)bh * S_ * HD;
#pragma unroll
    for (int i = 0; i < 4; i++) {
        int r = rowBlock + ty * 4 + i;
#pragma unroll
        for (int j = 0; j < 4; j++) O[(size_t)r * HD + tx * 4 + j] = acc[i][j];
    }
}

// ---------------------------------------------------------------------------
// 7) out = gather(att) @ Wproj + bproj   (4096x768, K=768)
//    A[i][c] gathers across heads: c -> (head=c/64, d=c%64)
// ---------------------------------------------------------------------------
__global__ __launch_bounds__(256) void k_proj(const float* __restrict__ Wp,
                                              const float* __restrict__ bp,
                                              float* __restrict__ out) {
    __shared__ float As[16][TS];
    __shared__ float Bs[16][TS];
    const int colBlock = blockIdx.x * 64;
    const int rowBlock = blockIdx.y * 64;
    const int tid = threadIdx.x;
    const int tx = tid & 15, ty = tid >> 4;
    float acc[4][4] = {};

    for (int kt = 0; kt < C_; kt += 16) {
#pragma unroll
        for (int i = 0; i < 4; i++) {
            int idx = tid + i * 256;
            int r = idx >> 4, c = idx & 15;
            int row = rowBlock + r;
            int b = row >> 10, s = row & 1023;
            int cc = kt + c;
            int head = cc >> 6, d = cc & 63;
            As[c][r] = g_att[(((size_t)(b * NH + head)) * S_ + s) * HD + d];
        }
#pragma unroll
        for (int i = 0; i < 4; i++) {
            int idx = tid + i * 256;
            int r = idx >> 6, c = idx & 63;
            Bs[r][c] = Wp[(size_t)(kt + r) * C_ + colBlock + c];
        }
        __syncthreads();
#pragma unroll
        for (int kk = 0; kk < 16; kk++) {
            float4 a4 = *(const float4*)&As[kk][ty * 4];
            float4 b4 = *(const float4*)&Bs[kk][tx * 4];
            float av[4] = {a4.x, a4.y, a4.z, a4.w};
            float bv[4] = {b4.x, b4.y, b4.z, b4.w};
#pragma unroll
            for (int i = 0; i < 4; i++)
#pragma unroll
                for (int j = 0; j < 4; j++) acc[i][j] += av[i] * bv[j];
        }
        __syncthreads();
    }
#pragma unroll
    for (int i = 0; i < 4; i++) {
        int r = rowBlock + ty * 4 + i;
#pragma unroll
        for (int j = 0; j < 4; j++) {
            int col = colBlock + tx * 4 + j;
            out[(size_t)r * C_ + col] = acc[i][j] + bp[col];
        }
    }
}

// ---------------------------------------------------------------------------
extern "C" void kernel_launch(void* const* d_in, const int* in_sizes, int n_in,
                              void* d_out, int out_size) {
    const float* x     = (const float*)d_in[0];
    const float* Wqkv  = (const float*)d_in[1];
    const float* Wproj = (const float*)d_in[2];
    const float* bproj = (const float*)d_in[3];
    const float* rph   = (const float*)d_in[4];
    const float* rpw   = (const float*)d_in[5];
    float* out = (float*)d_out;

    k_qkv<<<dim3(C3 / 64, (B_ * S_) / 64), 256>>>(x, Wqkv);
    k_relh<<<dim3(HH, BH), 256>>>(rph);
    k_relw<<<dim3(WW, BH), 256>>>(rpw);
    k_scores<<<dim3(S_ / 64, S_ / 64, BH), 256>>>();
    k_softmax<<<BH * S_, 256>>>();
    k_av<<<dim3(1, S_ / 64, BH), 256>>>();
    k_proj<<<dim3(C_ / 64, (B_ * S_) / 64), 256>>>(Wproj, bproj, out);
}

// round 3
// speedup vs baseline: 1.2089x; 1.2089x over previous
#include <cuda_runtime.h>
#include <math.h>

// Problem constants
#define B_    4
#define NH    12
#define BH    48            // B_*NH
#define S_    1024
#define HD    64
#define HH    32
#define WW    32
#define C_    768
#define C3    2304
#define SCALE 0.125f        // 64^-0.5

// ---------------- scratch (device globals: allocation-free rule) ------------
__device__ float g_q[BH * S_ * HD];
__device__ float g_k[BH * S_ * HD];
__device__ float g_v[BH * S_ * HD];
__device__ float g_relh[BH * S_ * HH];
__device__ float g_relw[BH * S_ * WW];
__device__ float g_scores[(size_t)BH * S_ * S_];  // 201 MB
__device__ float g_att[BH * S_ * HD];

// Shared-tile strides (pad to keep 16B row alignment, break conflicts)
#define TSA 132   // for 128-wide tiles
#define TSB 132

// ===========================================================================
// 1) qkv = x @ Wqkv  (4096 x 2304, K=768), scatter to per-head q/k/v
//    128x128 block, 256 threads, 8x8 micro-tile
// ===========================================================================
__global__ __launch_bounds__(256, 2) void k_qkv(const float* __restrict__ X,
                                                const float* __restrict__ W) {
    __shared__ float As[16][TSA];   // [k][m]
    __shared__ float Bs[16][TSB];   // [k][n]
    const int colBlock = blockIdx.x * 128;
    const int rowBlock = blockIdx.y * 128;
    const int tid = threadIdx.x;
    const int tx = tid & 15, ty = tid >> 4;
    float acc[8][8] = {};

    for (int kt = 0; kt < C_; kt += 16) {
        // A tile: 128 rows x 16 k  (512 float4, 2/thread) -> transposed store
#pragma unroll
        for (int i = 0; i < 2; i++) {
            int f4 = tid + i * 256;
            int r = f4 >> 2, c4 = f4 & 3;
            float4 v = *(const float4*)&X[(size_t)(rowBlock + r) * C_ + kt + c4 * 4];
            As[c4 * 4 + 0][r] = v.x; As[c4 * 4 + 1][r] = v.y;
            As[c4 * 4 + 2][r] = v.z; As[c4 * 4 + 3][r] = v.w;
        }
        // B tile: 16 k x 128 cols (512 float4, 2/thread) -> direct
#pragma unroll
        for (int i = 0; i < 2; i++) {
            int f4 = tid + i * 256;
            int r = f4 >> 5, c4 = f4 & 31;
            float4 v = *(const float4*)&W[(size_t)(kt + r) * C3 + colBlock + c4 * 4];
            *(float4*)&Bs[r][c4 * 4] = v;
        }
        __syncthreads();
#pragma unroll
        for (int kk = 0; kk < 16; kk++) {
            float4 a0 = *(const float4*)&As[kk][ty * 8];
            float4 a1 = *(const float4*)&As[kk][ty * 8 + 4];
            float4 b0 = *(const float4*)&Bs[kk][tx * 8];
            float4 b1 = *(const float4*)&Bs[kk][tx * 8 + 4];
            float a[8] = {a0.x, a0.y, a0.z, a0.w, a1.x, a1.y, a1.z, a1.w};
            float b[8] = {b0.x, b0.y, b0.z, b0.w, b1.x, b1.y, b1.z, b1.w};
#pragma unroll
            for (int i = 0; i < 8; i++)
#pragma unroll
                for (int j = 0; j < 8; j++) acc[i][j] += a[i] * b[j];
        }
        __syncthreads();
    }
    // scatter: col -> (part, head, d); row -> (b, s). 128-col tile stays in one
    // part; each float4 run stays in one head (64 | 8-runs).
#pragma unroll
    for (int i = 0; i < 8; i++) {
        int row = rowBlock + ty * 8 + i;
        int b = row >> 10, s = row & 1023;
#pragma unroll
        for (int jj = 0; jj < 8; jj += 4) {
            int col = colBlock + tx * 8 + jj;
            int part = col / C_;
            int rem = col - part * C_;
            int head = rem >> 6, d = rem & 63;
            float* dst = (part == 0) ? g_q : (part == 1) ? g_k : g_v;
            float4 st = make_float4(acc[i][jj], acc[i][jj + 1], acc[i][jj + 2], acc[i][jj + 3]);
            *(float4*)&dst[(((size_t)(b * NH + head)) * S_ + s) * HD + d] = st;
        }
    }
}

// ===========================================================================
// 2) rel_h[bh, h*32+w, kh] = sum_c q * RH[h-kh+31, c]   one block per (bh,h)
// ===========================================================================
__global__ __launch_bounds__(256) void k_relh(const float* __restrict__ RH) {
    const int h = blockIdx.x, bh = blockIdx.y;
    __shared__ float Qs[32][HD + 1];
    __shared__ float Rs[32][HD + 1];
    const int tid = threadIdx.x;
#pragma unroll
    for (int i = 0; i < 8; i++) {
        int idx = tid + i * 256;
        int r = idx >> 6, c = idx & 63;
        Qs[r][c] = g_q[((size_t)bh * S_ + h * 32 + r) * HD + c];
        Rs[r][c] = RH[(h - r + 31) * HD + c];
    }
    __syncthreads();
    for (int e = tid; e < 1024; e += 256) {
        int w = e >> 5, kh = e & 31;
        float acc = 0.f;
#pragma unroll
        for (int c = 0; c < HD; c++) acc += Qs[w][c] * Rs[kh][c];
        g_relh[((size_t)bh * S_ + h * 32 + w) * 32 + kh] = acc;
    }
}

__global__ __launch_bounds__(256) void k_relw(const float* __restrict__ RW) {
    const int w = blockIdx.x, bh = blockIdx.y;
    __shared__ float Qs[32][HD + 1];
    __shared__ float Rs[32][HD + 1];
    const int tid = threadIdx.x;
#pragma unroll
    for (int i = 0; i < 8; i++) {
        int idx = tid + i * 256;
        int r = idx >> 6, c = idx & 63;
        Qs[r][c] = g_q[((size_t)bh * S_ + r * 32 + w) * HD + c];
        Rs[r][c] = RW[(w - r + 31) * HD + c];
    }
    __syncthreads();
    for (int e = tid; e < 1024; e += 256) {
        int hh = e >> 5, kw = e & 31;
        float acc = 0.f;
#pragma unroll
        for (int c = 0; c < HD; c++) acc += Qs[hh][c] * Rs[kw][c];
        g_relw[((size_t)bh * S_ + hh * 32 + w) * 32 + kw] = acc;
    }
}

// ===========================================================================
// 4) scores[bh] = SCALE * q @ k^T + bias   (1024x1024, K=64)
//    128x128 block, 8x8 micro-tile, fused bias epilogue
// ===========================================================================
__global__ __launch_bounds__(256, 2) void k_scores() {
    const int bh = blockIdx.z;
    const int colBlock = blockIdx.x * 128;
    const int rowBlock = blockIdx.y * 128;
    const float* __restrict__ Q = g_q + (size_t)bh * S_ * HD;
    const float* __restrict__ K = g_k + (size_t)bh * S_ * HD;
    __shared__ float As[16][TSA];
    __shared__ float Bs[16][TSB];
    const int tid = threadIdx.x;
    const int tx = tid & 15, ty = tid >> 4;
    float acc[8][8] = {};

    for (int kt = 0; kt < HD; kt += 16) {
#pragma unroll
        for (int i = 0; i < 2; i++) {           // Q tile -> As[k][m]
            int f4 = tid + i * 256;
            int r = f4 >> 2, c4 = f4 & 3;
            float4 v = *(const float4*)&Q[(size_t)(rowBlock + r) * HD + kt + c4 * 4];
            As[c4 * 4 + 0][r] = v.x; As[c4 * 4 + 1][r] = v.y;
            As[c4 * 4 + 2][r] = v.z; As[c4 * 4 + 3][r] = v.w;
        }
#pragma unroll
        for (int i = 0; i < 2; i++) {           // K tile -> Bs[k][n]
            int f4 = tid + i * 256;
            int n = f4 >> 2, c4 = f4 & 3;
            float4 v = *(const float4*)&K[(size_t)(colBlock + n) * HD + kt + c4 * 4];
            Bs[c4 * 4 + 0][n] = v.x; Bs[c4 * 4 + 1][n] = v.y;
            Bs[c4 * 4 + 2][n] = v.z; Bs[c4 * 4 + 3][n] = v.w;
        }
        __syncthreads();
#pragma unroll
        for (int kk = 0; kk < 16; kk++) {
            float4 a0 = *(const float4*)&As[kk][ty * 8];
            float4 a1 = *(const float4*)&As[kk][ty * 8 + 4];
            float4 b0 = *(const float4*)&Bs[kk][tx * 8];
            float4 b1 = *(const float4*)&Bs[kk][tx * 8 + 4];
            float a[8] = {a0.x, a0.y, a0.z, a0.w, a1.x, a1.y, a1.z, a1.w};
            float b[8] = {b0.x, b0.y, b0.z, b0.w, b1.x, b1.y, b1.z, b1.w};
#pragma unroll
            for (int i = 0; i < 8; i++)
#pragma unroll
                for (int j = 0; j < 8; j++) acc[i][j] += a[i] * b[j];
        }
        __syncthreads();
    }
    float* Sout = g_scores + (size_t)bh * S_ * S_;
    const int ks0 = colBlock + tx * 8;          // ks>>5 constant over the 8-run
#pragma unroll
    for (int i = 0; i < 8; i++) {
        int qs = rowBlock + ty * 8 + i;
        const float* rh = g_relh + ((size_t)bh * S_ + qs) * 32;
        const float* rw = g_relw + ((size_t)bh * S_ + qs) * 32;
        float rhv = rh[ks0 >> 5];
#pragma unroll
        for (int jj = 0; jj < 8; jj += 4) {
            float4 st;
            st.x = SCALE * acc[i][jj + 0] + rhv + rw[(ks0 + jj + 0) & 31];
            st.y = SCALE * acc[i][jj + 1] + rhv + rw[(ks0 + jj + 1) & 31];
            st.z = SCALE * acc[i][jj + 2] + rhv + rw[(ks0 + jj + 2) & 31];
            st.w = SCALE * acc[i][jj + 3] + rhv + rw[(ks0 + jj + 3) & 31];
            *(float4*)&Sout[(size_t)qs * S_ + ks0 + jj] = st;
        }
    }
}

// ===========================================================================
// 5) row softmax (1024), 256 threads, float4 per thread
// ===========================================================================
__global__ __launch_bounds__(256) void k_softmax() {
    const size_t row = blockIdx.x;
    float4* p = (float4*)(g_scores + row * S_);
    const int tid = threadIdx.x;
    __shared__ float red[256];

    float4 v = p[tid];
    float m = fmaxf(fmaxf(v.x, v.y), fmaxf(v.z, v.w));
    red[tid] = m;
    __syncthreads();
    for (int s = 128; s > 0; s >>= 1) {
        if (tid < s) red[tid] = fmaxf(red[tid], red[tid + s]);
        __syncthreads();
    }
    m = red[0];
    __syncthreads();

    v.x = __expf(v.x - m); v.y = __expf(v.y - m);
    v.z = __expf(v.z - m); v.w = __expf(v.w - m);
    red[tid] = v.x + v.y + v.z + v.w;
    __syncthreads();
    for (int s = 128; s > 0; s >>= 1) {
        if (tid < s) red[tid] += red[tid + s];
        __syncthreads();
    }
    float inv = 1.f / red[0];
    v.x *= inv; v.y *= inv; v.z *= inv; v.w *= inv;
    p[tid] = v;
}

// ===========================================================================
// 6) att[bh] = P @ v   (1024x64, K=1024). 128x64 block, 128 threads, 8x8
// ===========================================================================
__global__ __launch_bounds__(128, 4) void k_av() {
    const int bh = blockIdx.y;
    const int rowBlock = blockIdx.x * 128;
    const float* __restrict__ A = g_scores + (size_t)bh * S_ * S_;
    const float* __restrict__ V = g_v + (size_t)bh * S_ * HD;
    __shared__ float As[16][TSA];
    __shared__ float Bs[16][HD + 4];
    const int tid = threadIdx.x;
    const int tx = tid & 7, ty = tid >> 3;      // 8 x 16
    float acc[8][8] = {};

    for (int kt = 0; kt < S_; kt += 16) {
        // A tile 128x16 (512 f4, 4/thread) transposed
#pragma unroll
        for (int i = 0; i < 4; i++) {
            int f4 = tid + i * 128;
            int r = f4 >> 2, c4 = f4 & 3;
            float4 v = *(const float4*)&A[(size_t)(rowBlock + r) * S_ + kt + c4 * 4];
            As[c4 * 4 + 0][r] = v.x; As[c4 * 4 + 1][r] = v.y;
            As[c4 * 4 + 2][r] = v.z; As[c4 * 4 + 3][r] = v.w;
        }
        // B tile 16x64 (256 f4, 2/thread)
#pragma unroll
        for (int i = 0; i < 2; i++) {
            int f4 = tid + i * 128;
            int r = f4 >> 4, c4 = f4 & 15;
            float4 v = *(const float4*)&V[(size_t)(kt + r) * HD + c4 * 4];
            *(float4*)&Bs[r][c4 * 4] = v;
        }
        __syncthreads();
#pragma unroll
        for (int kk = 0; kk < 16; kk++) {
            float4 a0 = *(const float4*)&As[kk][ty * 8];
            float4 a1 = *(const float4*)&As[kk][ty * 8 + 4];
            float4 b0 = *(const float4*)&Bs[kk][tx * 8];
            float4 b1 = *(const float4*)&Bs[kk][tx * 8 + 4];
            float a[8] = {a0.x, a0.y, a0.z, a0.w, a1.x, a1.y, a1.z, a1.w};
            float b[8] = {b0.x, b0.y, b0.z, b0.w, b1.x, b1.y, b1.z, b1.w};
#pragma unroll
            for (int i = 0; i < 8; i++)
#pragma unroll
                for (int j = 0; j < 8; j++) acc[i][j] += a[i] * b[j];
        }
        __syncthreads();
    }
    float* O = g_att + (size_t)bh * S_ * HD;
#pragma unroll
    for (int i = 0; i < 8; i++) {
        int r = rowBlock + ty * 8 + i;
#pragma unroll
        for (int jj = 0; jj < 8; jj += 4) {
            float4 st = make_float4(acc[i][jj], acc[i][jj + 1], acc[i][jj + 2], acc[i][jj + 3]);
            *(float4*)&O[(size_t)r * HD + tx * 8 + jj] = st;
        }
    }
}

// ===========================================================================
// 7) out = gather(att) @ Wproj + bproj   (4096x768, K=768)
// ===========================================================================
__global__ __launch_bounds__(256, 2) void k_proj(const float* __restrict__ Wp,
                                                 const float* __restrict__ bp,
                                                 float* __restrict__ out) {
    __shared__ float As[16][TSA];
    __shared__ float Bs[16][TSB];
    const int colBlock = blockIdx.x * 128;
    const int rowBlock = blockIdx.y * 128;
    const int tid = threadIdx.x;
    const int tx = tid & 15, ty = tid >> 4;
    float acc[8][8] = {};

    for (int kt = 0; kt < C_; kt += 16) {
#pragma unroll
        for (int i = 0; i < 2; i++) {           // gathered A tile
            int f4 = tid + i * 256;
            int r = f4 >> 2, c4 = f4 & 3;
            int row = rowBlock + r;
            int b = row >> 10, s = row & 1023;
            int cc = kt + c4 * 4;               // float4 stays within one head
            int head = cc >> 6, d = cc & 63;
            float4 v = *(const float4*)&g_att[(((size_t)(b * NH + head)) * S_ + s) * HD + d];
            As[c4 * 4 + 0][r] = v.x; As[c4 * 4 + 1][r] = v.y;
            As[c4 * 4 + 2][r] = v.z; As[c4 * 4 + 3][r] = v.w;
        }
#pragma unroll
        for (int i = 0; i < 2; i++) {
            int f4 = tid + i * 256;
            int r = f4 >> 5, c4 = f4 & 31;
            float4 v = *(const float4*)&Wp[(size_t)(kt + r) * C_ + colBlock + c4 * 4];
            *(float4*)&Bs[r][c4 * 4] = v;
        }
        __syncthreads();
#pragma unroll
        for (int kk = 0; kk < 16; kk++) {
            float4 a0 = *(const float4*)&As[kk][ty * 8];
            float4 a1 = *(const float4*)&As[kk][ty * 8 + 4];
            float4 b0 = *(const float4*)&Bs[kk][tx * 8];
            float4 b1 = *(const float4*)&Bs[kk][tx * 8 + 4];
            float a[8] = {a0.x, a0.y, a0.z, a0.w, a1.x, a1.y, a1.z, a1.w};
            float b[8] = {b0.x, b0.y, b0.z, b0.w, b1.x, b1.y, b1.z, b1.w};
#pragma unroll
            for (int i = 0; i < 8; i++)
#pragma unroll
                for (int j = 0; j < 8; j++) acc[i][j] += a[i] * b[j];
        }
        __syncthreads();
    }
#pragma unroll
    for (int i = 0; i < 8; i++) {
        int r = rowBlock + ty * 8 + i;
#pragma unroll
        for (int jj = 0; jj < 8; jj += 4) {
            int col = colBlock + tx * 8 + jj;
            float4 bv = *(const float4*)&bp[col];
            float4 st = make_float4(acc[i][jj] + bv.x, acc[i][jj + 1] + bv.y,
                                    acc[i][jj + 2] + bv.z, acc[i][jj + 3] + bv.w);
            *(float4*)&out[(size_t)r * C_ + col] = st;
        }
    }
}

// ---------------------------------------------------------------------------
extern "C" void kernel_launch(void* const* d_in, const int* in_sizes, int n_in,
                              void* d_out, int out_size) {
    const float* x     = (const float*)d_in[0];
    const float* Wqkv  = (const float*)d_in[1];
    const float* Wproj = (const float*)d_in[2];
    const float* bproj = (const float*)d_in[3];
    const float* rph   = (const float*)d_in[4];
    const float* rpw   = (const float*)d_in[5];
    float* out = (float*)d_out;

    k_qkv<<<dim3(C3 / 128, (B_ * S_) / 128), 256>>>(x, Wqkv);
    k_relh<<<dim3(HH, BH), 256>>>(rph);
    k_relw<<<dim3(WW, BH), 256>>>(rpw);
    k_scores<<<dim3(S_ / 128, S_ / 128, BH), 256>>>();
    k_softmax<<<BH * S_, 256>>>();
    k_av<<<dim3(S_ / 128, BH), 128>>>();
    k_proj<<<dim3(C_ / 128, (B_ * S_) / 128), 256>>>(Wproj, bproj, out);
}

// round 5
// speedup vs baseline: 1.5523x; 1.2841x over previous
#include <cuda_runtime.h>
#include <cuda_bf16.h>
#include <cstdint>
#include <math.h>

// Problem constants
#define B_    4
#define NH    12
#define BH    48
#define S_    1024
#define HD    64
#define C_    768
#define C3    2304
#define SCALE 0.125f

// ---------------- scratch ----------------
__device__ float g_q[BH * S_ * HD];
__device__ float g_k[BH * S_ * HD];
__device__ float g_v[BH * S_ * HD];
__device__ float g_relh[BH * S_ * 32];
__device__ float g_relw[BH * S_ * 32];
__device__ float g_scores[(size_t)BH * S_ * S_];
__device__ float g_att[BH * S_ * HD];

// ---------------- mma.sync helpers (sm_80+, valid on plain sm_103) ----------
__device__ __forceinline__ uint32_t smem_u32(const void* p) {
    uint32_t a;
    asm("{ .reg .u64 t; cvta.to.shared.u64 t, %1; cvt.u32.u64 %0, t; }" : "=r"(a) : "l"(p));
    return a;
}

#define LDSM4(r, addr) \
    asm volatile("ldmatrix.sync.aligned.m8n8.x4.shared.b16 {%0,%1,%2,%3}, [%4];" \
        : "=r"((r)[0]), "=r"((r)[1]), "=r"((r)[2]), "=r"((r)[3]) : "r"(addr))

__device__ __forceinline__ void mma16816(float* c, const uint32_t* a, const uint32_t* b) {
    asm volatile("mma.sync.aligned.m16n8k16.row.col.f32.bf16.bf16.f32 "
        "{%0,%1,%2,%3}, {%4,%5,%6,%7}, {%8,%9}, {%0,%1,%2,%3};"
        : "+f"(c[0]), "+f"(c[1]), "+f"(c[2]), "+f"(c[3])
        : "r"(a[0]), "r"(a[1]), "r"(a[2]), "r"(a[3]), "r"(b[0]), "r"(b[1]));
}

// float4 -> bf16 hi/lo, stored K-major at [r][c..c+3] (8B each)
__device__ __forceinline__ void cvtst4(__nv_bfloat16* ph, __nv_bfloat16* pl, float4 v) {
    __nv_bfloat16 h0 = __float2bfloat16(v.x), h1 = __float2bfloat16(v.y);
    __nv_bfloat16 h2 = __float2bfloat16(v.z), h3 = __float2bfloat16(v.w);
    __nv_bfloat162 H0 = __halves2bfloat162(h0, h1), H1 = __halves2bfloat162(h2, h3);
    *(uint2*)ph = make_uint2(*(uint32_t*)&H0, *(uint32_t*)&H1);
    __nv_bfloat162 L0 = __halves2bfloat162(__float2bfloat16(v.x - __bfloat162float(h0)),
                                           __float2bfloat16(v.y - __bfloat162float(h1)));
    __nv_bfloat162 L1 = __halves2bfloat162(__float2bfloat16(v.z - __bfloat162float(h2)),
                                           __float2bfloat16(v.w - __bfloat162float(h3)));
    *(uint2*)pl = make_uint2(*(uint32_t*)&L0, *(uint32_t*)&L1);
}

// fragment address helpers (row stride 40 bf16 = 80B, conflict-free for ldmatrix)
#define A_ADDR(T, mBase, kk) smem_u32(&(T)[(mBase) + (lane & 15)][(kk) + (lane >> 4) * 8])
#define B_ADDR(T, nBase, kk) \
    smem_u32(&(T)[(nBase) + (lane & 7) + ((lane >> 4) & 1) * 8][(kk) + ((lane >> 3) & 1) * 8])

// ===========================================================================
// 1) qkv = x @ Wqkv (4096x2304, K=768) -> scatter q/k/v
// ===========================================================================
__global__ __launch_bounds__(256) void k_qkv(const float* __restrict__ X,
                                             const float* __restrict__ W) {
    __shared__ __align__(16) __nv_bfloat16 Ah[128][40], Al[128][40];
    __shared__ __align__(16) __nv_bfloat16 Bh[128][40], Bl[128][40];
    const int tid = threadIdx.x, lane = tid & 31, warp = tid >> 5;
    const int wm = warp & 3, wn = warp >> 2;              // 4 x 2 warp grid
    const int rowBlock = blockIdx.y * 128, colBlock = blockIdx.x * 128;
    float c[2][8][4] = {};

    for (int kt = 0; kt < C_; kt += 32) {
#pragma unroll
        for (int i = 0; i < 4; i++) {                     // A tile 128x32
            int f4 = tid + i * 256;
            int r = f4 >> 3, cc = (f4 & 7) * 4;
            float4 v = *(const float4*)&X[(size_t)(rowBlock + r) * C_ + kt + cc];
            cvtst4(&Ah[r][cc], &Al[r][cc], v);
        }
#pragma unroll
        for (int i = 0; i < 16; i++) {                    // B transpose (coalesced)
            int idx = tid + i * 256;
            int k = idx >> 7, n = idx & 127;
            float v = W[(size_t)(kt + k) * C3 + colBlock + n];
            __nv_bfloat16 h = __float2bfloat16(v);
            Bh[n][k] = h;
            Bl[n][k] = __float2bfloat16(v - __bfloat162float(h));
        }
        __syncthreads();
#pragma unroll
        for (int kk = 0; kk < 32; kk += 16) {
            uint32_t ah[2][4], al[2][4];
#pragma unroll
            for (int mf = 0; mf < 2; mf++) {
                LDSM4(ah[mf], A_ADDR(Ah, wm * 32 + mf * 16, kk));
                LDSM4(al[mf], A_ADDR(Al, wm * 32 + mf * 16, kk));
            }
#pragma unroll
            for (int p = 0; p < 4; p++) {
                uint32_t bhf[4], blf[4];
                LDSM4(bhf, B_ADDR(Bh, wn * 64 + p * 16, kk));
                LDSM4(blf, B_ADDR(Bl, wn * 64 + p * 16, kk));
#pragma unroll
                for (int mf = 0; mf < 2; mf++)
#pragma unroll
                    for (int nt = 0; nt < 2; nt++) {
                        float* cc_ = c[mf][p * 2 + nt];
                        mma16816(cc_, ah[mf], bhf + nt * 2);
                        mma16816(cc_, ah[mf], blf + nt * 2);
                        mma16816(cc_, al[mf], bhf + nt * 2);
                    }
            }
        }
        __syncthreads();
    }
    const int col0 = colBlock + wn * 64;
    const int part = col0 / C_;
    const int rem = col0 - part * C_;
    const int head = rem >> 6;
    float* dst = (part == 0) ? g_q : (part == 1) ? g_k : g_v;
#pragma unroll
    for (int mf = 0; mf < 2; mf++) {
        int m0 = rowBlock + wm * 32 + mf * 16 + (lane >> 2);
#pragma unroll
        for (int h8 = 0; h8 < 2; h8++) {
            int m = m0 + h8 * 8;
            int b = m >> 10, s = m & 1023;
            float* base = &dst[(((size_t)(b * NH + head)) * S_ + s) * HD];
#pragma unroll
            for (int nf = 0; nf < 8; nf++) {
                float2 st = make_float2(c[mf][nf][h8 * 2], c[mf][nf][h8 * 2 + 1]);
                *(float2*)&base[nf * 8 + (lane & 3) * 2] = st;
            }
        }
    }
}

// ===========================================================================
// rel bias kernels (fp32, small)
// ===========================================================================
__global__ __launch_bounds__(256) void k_relh(const float* __restrict__ RH) {
    const int h = blockIdx.x, bh = blockIdx.y;
    __shared__ float Qs[32][HD + 1], Rs[32][HD + 1];
    const int tid = threadIdx.x;
#pragma unroll
    for (int i = 0; i < 8; i++) {
        int idx = tid + i * 256;
        int r = idx >> 6, c = idx & 63;
        Qs[r][c] = g_q[((size_t)bh * S_ + h * 32 + r) * HD + c];
        Rs[r][c] = RH[(h - r + 31) * HD + c];
    }
    __syncthreads();
    for (int e = tid; e < 1024; e += 256) {
        int w = e >> 5, kh = e & 31;
        float acc = 0.f;
#pragma unroll
        for (int c = 0; c < HD; c++) acc += Qs[w][c] * Rs[kh][c];
        g_relh[((size_t)bh * S_ + h * 32 + w) * 32 + kh] = acc;
    }
}
__global__ __launch_bounds__(256) void k_relw(const float* __restrict__ RW) {
    const int w = blockIdx.x, bh = blockIdx.y;
    __shared__ float Qs[32][HD + 1], Rs[32][HD + 1];
    const int tid = threadIdx.x;
#pragma unroll
    for (int i = 0; i < 8; i++) {
        int idx = tid + i * 256;
        int r = idx >> 6, c = idx & 63;
        Qs[r][c] = g_q[((size_t)bh * S_ + r * 32 + w) * HD + c];
        Rs[r][c] = RW[(w - r + 31) * HD + c];
    }
    __syncthreads();
    for (int e = tid; e < 1024; e += 256) {
        int hh = e >> 5, kw = e & 31;
        float acc = 0.f;
#pragma unroll
        for (int c = 0; c < HD; c++) acc += Qs[hh][c] * Rs[kw][c];
        g_relw[((size_t)bh * S_ + hh * 32 + w) * 32 + kw] = acc;
    }
}

// ===========================================================================
// 2) scores = SCALE * q@k^T + bias  (per bh, 128x128, K=64)
// ===========================================================================
__global__ __launch_bounds__(256) void k_scores() {
    __shared__ __align__(16) __nv_bfloat16 Ah[128][40], Al[128][40];
    __shared__ __align__(16) __nv_bfloat16 Bh[128][40], Bl[128][40];
    const int tid = threadIdx.x, lane = tid & 31, warp = tid >> 5;
    const int wm = warp & 3, wn = warp >> 2;
    const int bh = blockIdx.z;
    const int rowBlock = blockIdx.y * 128, colBlock = blockIdx.x * 128;
    const float* __restrict__ Q = g_q + (size_t)bh * S_ * HD;
    const float* __restrict__ K = g_k + (size_t)bh * S_ * HD;
    float c[2][8][4] = {};

    for (int kt = 0; kt < HD; kt += 32) {
#pragma unroll
        for (int i = 0; i < 4; i++) {
            int f4 = tid + i * 256;
            int r = f4 >> 3, cc = (f4 & 7) * 4;
            float4 v = *(const float4*)&Q[(size_t)(rowBlock + r) * HD + kt + cc];
            cvtst4(&Ah[r][cc], &Al[r][cc], v);
        }
#pragma unroll
        for (int i = 0; i < 4; i++) {                     // K is [n][k] already
            int f4 = tid + i * 256;
            int r = f4 >> 3, cc = (f4 & 7) * 4;
            float4 v = *(const float4*)&K[(size_t)(colBlock + r) * HD + kt + cc];
            cvtst4(&Bh[r][cc], &Bl[r][cc], v);
        }
        __syncthreads();
#pragma unroll
        for (int kk = 0; kk < 32; kk += 16) {
            uint32_t ah[2][4], al[2][4];
#pragma unroll
            for (int mf = 0; mf < 2; mf++) {
                LDSM4(ah[mf], A_ADDR(Ah, wm * 32 + mf * 16, kk));
                LDSM4(al[mf], A_ADDR(Al, wm * 32 + mf * 16, kk));
            }
#pragma unroll
            for (int p = 0; p < 4; p++) {
                uint32_t bhf[4], blf[4];
                LDSM4(bhf, B_ADDR(Bh, wn * 64 + p * 16, kk));
                LDSM4(blf, B_ADDR(Bl, wn * 64 + p * 16, kk));
#pragma unroll
                for (int mf = 0; mf < 2; mf++)
#pragma unroll
                    for (int nt = 0; nt < 2; nt++) {
                        float* cc_ = c[mf][p * 2 + nt];
                        mma16816(cc_, ah[mf], bhf + nt * 2);
                        mma16816(cc_, ah[mf], blf + nt * 2);
                        mma16816(cc_, al[mf], bhf + nt * 2);
                    }
            }
        }
        __syncthreads();
    }
    const int col0 = colBlock + wn * 64;
#pragma unroll
    for (int mf = 0; mf < 2; mf++) {
        int m0 = rowBlock + wm * 32 + mf * 16 + (lane >> 2);
#pragma unroll
        for (int h8 = 0; h8 < 2; h8++) {
            int qs = m0 + h8 * 8;
            const float* rh = g_relh + ((size_t)bh * S_ + qs) * 32;
            const float* rw = g_relw + ((size_t)bh * S_ + qs) * 32;
            float* Srow = g_scores + ((size_t)bh * S_ + qs) * S_;
#pragma unroll
            for (int nf = 0; nf < 8; nf++) {
                int n = col0 + nf * 8 + (lane & 3) * 2;
                float rhv = rh[n >> 5];
                float2 st = make_float2(SCALE * c[mf][nf][h8 * 2] + rhv + rw[n & 31],
                                        SCALE * c[mf][nf][h8 * 2 + 1] + rhv + rw[(n & 31) + 1]);
                *(float2*)&Srow[n] = st;
            }
        }
    }
}

// ===========================================================================
// 3) softmax rows
// ===========================================================================
__global__ __launch_bounds__(256) void k_softmax() {
    const size_t row = blockIdx.x;
    float4* p = (float4*)(g_scores + row * S_);
    const int tid = threadIdx.x;
    __shared__ float red[256];
    float4 v = p[tid];
    float m = fmaxf(fmaxf(v.x, v.y), fmaxf(v.z, v.w));
    red[tid] = m; __syncthreads();
    for (int s = 128; s > 0; s >>= 1) { if (tid < s) red[tid] = fmaxf(red[tid], red[tid + s]); __syncthreads(); }
    m = red[0]; __syncthreads();
    v.x = __expf(v.x - m); v.y = __expf(v.y - m); v.z = __expf(v.z - m); v.w = __expf(v.w - m);
    red[tid] = v.x + v.y + v.z + v.w; __syncthreads();
    for (int s = 128; s > 0; s >>= 1) { if (tid < s) red[tid] += red[tid + s]; __syncthreads(); }
    float inv = 1.f / red[0];
    v.x *= inv; v.y *= inv; v.z *= inv; v.w *= inv;
    p[tid] = v;
}

// ===========================================================================
// 4) att = P @ V  (128x64 tiles, K=1024)
// ===========================================================================
__global__ __launch_bounds__(256) void k_av() {
    __shared__ __align__(16) __nv_bfloat16 Ah[128][40], Al[128][40];
    __shared__ __align__(16) __nv_bfloat16 Bh[64][40], Bl[64][40];
    const int tid = threadIdx.x, lane = tid & 31, warp = tid >> 5;
    const int bh = blockIdx.y;
    const int rowBlock = blockIdx.x * 128;
    const float* __restrict__ A = g_scores + (size_t)bh * S_ * S_;
    const float* __restrict__ V = g_v + (size_t)bh * S_ * HD;
    float c[8][4] = {};

    for (int kt = 0; kt < S_; kt += 32) {
#pragma unroll
        for (int i = 0; i < 4; i++) {
            int f4 = tid + i * 256;
            int r = f4 >> 3, cc = (f4 & 7) * 4;
            float4 v = *(const float4*)&A[(size_t)(rowBlock + r) * S_ + kt + cc];
            cvtst4(&Ah[r][cc], &Al[r][cc], v);
        }
#pragma unroll
        for (int i = 0; i < 8; i++) {                     // V transpose (coalesced)
            int idx = tid + i * 256;
            int ks = idx >> 6, nd = idx & 63;
            float v = V[(size_t)(kt + ks) * HD + nd];
            __nv_bfloat16 h = __float2bfloat16(v);
            Bh[nd][ks] = h;
            Bl[nd][ks] = __float2bfloat16(v - __bfloat162float(h));
        }
        __syncthreads();
#pragma unroll
        for (int kk = 0; kk < 32; kk += 16) {
            uint32_t ah[4], al[4];
            LDSM4(ah, A_ADDR(Ah, warp * 16, kk));
            LDSM4(al, A_ADDR(Al, warp * 16, kk));
#pragma unroll
            for (int p = 0; p < 4; p++) {
                uint32_t bhf[4], blf[4];
                LDSM4(bhf, B_ADDR(Bh, p * 16, kk));
                LDSM4(blf, B_ADDR(Bl, p * 16, kk));
#pragma unroll
                for (int nt = 0; nt < 2; nt++) {
                    float* cc_ = c[p * 2 + nt];
                    mma16816(cc_, ah, bhf + nt * 2);
                    mma16816(cc_, ah, blf + nt * 2);
                    mma16816(cc_, al, bhf + nt * 2);
                }
            }
        }
        __syncthreads();
    }
    float* O = g_att + (size_t)bh * S_ * HD;
    int m0 = rowBlock + warp * 16 + (lane >> 2);
#pragma unroll
    for (int h8 = 0; h8 < 2; h8++) {
        int m = m0 + h8 * 8;
#pragma unroll
        for (int nf = 0; nf < 8; nf++) {
            float2 st = make_float2(c[nf][h8 * 2], c[nf][h8 * 2 + 1]);
            *(float2*)&O[(size_t)m * HD + nf * 8 + (lane & 3) * 2] = st;
        }
    }
}

// ===========================================================================
// 5) out = gather(att) @ Wproj + bproj  (4096x768, K=768)
// ===========================================================================
__global__ __launch_bounds__(256) void k_proj(const float* __restrict__ Wp,
                                              const float* __restrict__ bp,
                                              float* __restrict__ out) {
    __shared__ __align__(16) __nv_bfloat16 Ah[128][40], Al[128][40];
    __shared__ __align__(16) __nv_bfloat16 Bh[128][40], Bl[128][40];
    const int tid = threadIdx.x, lane = tid & 31, warp = tid >> 5;
    const int wm = warp & 3, wn = warp >> 2;
    const int rowBlock = blockIdx.y * 128, colBlock = blockIdx.x * 128;
    float c[2][8][4] = {};

    for (int kt = 0; kt < C_; kt += 32) {
#pragma unroll
        for (int i = 0; i < 4; i++) {                     // gathered A tile
            int f4 = tid + i * 256;
            int r = f4 >> 3, cc = (f4 & 7) * 4;
            int row = rowBlock + r;
            int b = row >> 10, s = row & 1023;
            int k = kt + cc;
            int head = k >> 6, d = k & 63;
            float4 v = *(const float4*)&g_att[(((size_t)(b * NH + head)) * S_ + s) * HD + d];
            cvtst4(&Ah[r][cc], &Al[r][cc], v);
        }
#pragma unroll
        for (int i = 0; i < 16; i++) {                    // Wp transpose
            int idx = tid + i * 256;
            int k = idx >> 7, n = idx & 127;
            float v = Wp[(size_t)(kt + k) * C_ + colBlock + n];
            __nv_bfloat16 h = __float2bfloat16(v);
            Bh[n][k] = h;
            Bl[n][k] = __float2bfloat16(v - __bfloat162float(h));
        }
        __syncthreads();
#pragma unroll
        for (int kk = 0; kk < 32; kk += 16) {
            uint32_t ah[2][4], al[2][4];
#pragma unroll
            for (int mf = 0; mf < 2; mf++) {
                LDSM4(ah[mf], A_ADDR(Ah, wm * 32 + mf * 16, kk));
                LDSM4(al[mf], A_ADDR(Al, wm * 32 + mf * 16, kk));
            }
#pragma unroll
            for (int p = 0; p < 4; p++) {
                uint32_t bhf[4], blf[4];
                LDSM4(bhf, B_ADDR(Bh, wn * 64 + p * 16, kk));
                LDSM4(blf, B_ADDR(Bl, wn * 64 + p * 16, kk));
#pragma unroll
                for (int mf = 0; mf < 2; mf++)
#pragma unroll
                    for (int nt = 0; nt < 2; nt++) {
                        float* cc_ = c[mf][p * 2 + nt];
                        mma16816(cc_, ah[mf], bhf + nt * 2);
                        mma16816(cc_, ah[mf], blf + nt * 2);
                        mma16816(cc_, al[mf], bhf + nt * 2);
                    }
            }
        }
        __syncthreads();
    }
    const int col0 = colBlock + wn * 64;
#pragma unroll
    for (int mf = 0; mf < 2; mf++) {
        int m0 = rowBlock + wm * 32 + mf * 16 + (lane >> 2);
#pragma unroll
        for (int h8 = 0; h8 < 2; h8++) {
            int m = m0 + h8 * 8;
#pragma unroll
            for (int nf = 0; nf < 8; nf++) {
                int n = col0 + nf * 8 + (lane & 3) * 2;
                float2 bv = *(const float2*)&bp[n];
                float2 st = make_float2(c[mf][nf][h8 * 2] + bv.x, c[mf][nf][h8 * 2 + 1] + bv.y);
                *(float2*)&out[(size_t)m * C_ + n] = st;
            }
        }
    }
}

// ---------------------------------------------------------------------------
extern "C" void kernel_launch(void* const* d_in, const int* in_sizes, int n_in,
                              void* d_out, int out_size) {
    const float* x     = (const float*)d_in[0];
    const float* Wqkv  = (const float*)d_in[1];
    const float* Wproj = (const float*)d_in[2];
    const float* bproj = (const float*)d_in[3];
    const float* rph   = (const float*)d_in[4];
    const float* rpw   = (const float*)d_in[5];
    float* out = (float*)d_out;

    k_qkv<<<dim3(C3 / 128, (B_ * S_) / 128), 256>>>(x, Wqkv);
    k_relh<<<dim3(32, BH), 256>>>(rph);
    k_relw<<<dim3(32, BH), 256>>>(rpw);
    k_scores<<<dim3(S_ / 128, S_ / 128, BH), 256>>>();
    k_softmax<<<BH * S_, 256>>>();
    k_av<<<dim3(S_ / 128, BH), 256>>>();
    k_proj<<<dim3(C_ / 128, (B_ * S_) / 128), 256>>>(Wproj, bproj, out);
}

// round 8
// speedup vs baseline: 2.2571x; 1.4540x over previous
#include <cuda_runtime.h>
#include <cuda_bf16.h>
#include <cstdint>
#include <math.h>

// Problem constants
#define B_    4
#define NH    12
#define BH    48
#define S_    1024
#define HD    64
#define C_    768
#define C3    2304
#define SCALE 0.125f

// ---------------- scratch ----------------
__device__ float g_q[BH * S_ * HD];
__device__ float g_k[BH * S_ * HD];
__device__ float g_v[BH * S_ * HD];
__device__ float g_relh[BH * S_ * 32];
__device__ float g_relw[BH * S_ * 32];
__device__ float g_att[BH * S_ * HD];

// ---------------- mma.sync helpers ----------------
__device__ __forceinline__ uint32_t smem_u32(const void* p) {
    uint32_t a;
    asm("{ .reg .u64 t; cvta.to.shared.u64 t, %1; cvt.u32.u64 %0, t; }" : "=r"(a) : "l"(p));
    return a;
}

#define LDSM4(r, addr) \
    asm volatile("ldmatrix.sync.aligned.m8n8.x4.shared.b16 {%0,%1,%2,%3}, [%4];" \
        : "=r"((r)[0]), "=r"((r)[1]), "=r"((r)[2]), "=r"((r)[3]) : "r"(addr))

__device__ __forceinline__ void mma16816(float* c, const uint32_t* a, const uint32_t* b) {
    asm volatile("mma.sync.aligned.m16n8k16.row.col.f32.bf16.bf16.f32 "
        "{%0,%1,%2,%3}, {%4,%5,%6,%7}, {%8,%9}, {%0,%1,%2,%3};"
        : "+f"(c[0]), "+f"(c[1]), "+f"(c[2]), "+f"(c[3])
        : "r"(a[0]), "r"(a[1]), "r"(a[2]), "r"(a[3]), "r"(b[0]), "r"(b[1]));
}

__device__ __forceinline__ uint32_t pkbf2(float x, float y) {
    __nv_bfloat162 t = __halves2bfloat162(__float2bfloat16(x), __float2bfloat16(y));
    return *reinterpret_cast<uint32_t*>(&t);
}

// float4 -> bf16 hi/lo at K-major slot (8B each)
__device__ __forceinline__ void cvtst4(__nv_bfloat16* ph, __nv_bfloat16* pl, float4 v) {
    __nv_bfloat16 h0 = __float2bfloat16(v.x), h1 = __float2bfloat16(v.y);
    __nv_bfloat16 h2 = __float2bfloat16(v.z), h3 = __float2bfloat16(v.w);
    __nv_bfloat162 H0 = __halves2bfloat162(h0, h1), H1 = __halves2bfloat162(h2, h3);
    *(uint2*)ph = make_uint2(*(uint32_t*)&H0, *(uint32_t*)&H1);
    __nv_bfloat162 L0 = __halves2bfloat162(__float2bfloat16(v.x - __bfloat162float(h0)),
                                           __float2bfloat16(v.y - __bfloat162float(h1)));
    __nv_bfloat162 L1 = __halves2bfloat162(__float2bfloat16(v.z - __bfloat162float(h2)),
                                           __float2bfloat16(v.w - __bfloat162float(h3)));
    *(uint2*)pl = make_uint2(*(uint32_t*)&L0, *(uint32_t*)&L1);
}

// fragment address helpers (40-elem row stride variants for the plain GEMMs)
#define A_ADDR(T, mBase, kk) smem_u32(&(T)[(mBase) + (lane & 15)][(kk) + (lane >> 4) * 8])
#define B_ADDR(T, nBase, kk) \
    smem_u32(&(T)[(nBase) + (lane & 7) + ((lane >> 4) & 1) * 8][(kk) + ((lane >> 3) & 1) * 8])
// pointer+stride versions for the flash kernel
#define A_ADDRP(P, st, mBase, kk) smem_u32((P) + ((mBase) + (lane & 15)) * (st) + (kk) + (lane >> 4) * 8)
#define B_ADDRP(P, st, nBase, kk) \
    smem_u32((P) + ((nBase) + (lane & 7) + ((lane >> 4) & 1) * 8) * (st) + (kk) + ((lane >> 3) & 1) * 8)

// ===========================================================================
// 1) qkv = x @ Wqkv (4096x2304, K=768) -> scatter q/k/v
// ===========================================================================
__global__ __launch_bounds__(256) void k_qkv(const float* __restrict__ X,
                                             const float* __restrict__ W) {
    __shared__ __align__(16) __nv_bfloat16 Ah[128][40], Al[128][40];
    __shared__ __align__(16) __nv_bfloat16 Bh[128][40], Bl[128][40];
    const int tid = threadIdx.x, lane = tid & 31, warp = tid >> 5;
    const int wm = warp & 3, wn = warp >> 2;
    const int rowBlock = blockIdx.y * 128, colBlock = blockIdx.x * 128;
    float c[2][8][4] = {};

    for (int kt = 0; kt < C_; kt += 32) {
#pragma unroll
        for (int i = 0; i < 4; i++) {
            int f4 = tid + i * 256;
            int r = f4 >> 3, cc = (f4 & 7) * 4;
            float4 v = *(const float4*)&X[(size_t)(rowBlock + r) * C_ + kt + cc];
            cvtst4(&Ah[r][cc], &Al[r][cc], v);
        }
#pragma unroll
        for (int i = 0; i < 16; i++) {
            int idx = tid + i * 256;
            int k = idx >> 7, n = idx & 127;
            float v = W[(size_t)(kt + k) * C3 + colBlock + n];
            __nv_bfloat16 h = __float2bfloat16(v);
            Bh[n][k] = h;
            Bl[n][k] = __float2bfloat16(v - __bfloat162float(h));
        }
        __syncthreads();
#pragma unroll
        for (int kk = 0; kk < 32; kk += 16) {
            uint32_t ah[2][4], al[2][4];
#pragma unroll
            for (int mf = 0; mf < 2; mf++) {
                LDSM4(ah[mf], A_ADDR(Ah, wm * 32 + mf * 16, kk));
                LDSM4(al[mf], A_ADDR(Al, wm * 32 + mf * 16, kk));
            }
#pragma unroll
            for (int p = 0; p < 4; p++) {
                uint32_t bhf[4], blf[4];
                LDSM4(bhf, B_ADDR(Bh, wn * 64 + p * 16, kk));
                LDSM4(blf, B_ADDR(Bl, wn * 64 + p * 16, kk));
#pragma unroll
                for (int mf = 0; mf < 2; mf++)
#pragma unroll
                    for (int nt = 0; nt < 2; nt++) {
                        float* cc_ = c[mf][p * 2 + nt];
                        mma16816(cc_, ah[mf], bhf + nt * 2);
                        mma16816(cc_, ah[mf], blf + nt * 2);
                        mma16816(cc_, al[mf], bhf + nt * 2);
                    }
            }
        }
        __syncthreads();
    }
    const int col0 = colBlock + wn * 64;
    const int part = col0 / C_;
    const int rem = col0 - part * C_;
    const int head = rem >> 6;
    float* dst = (part == 0) ? g_q : (part == 1) ? g_k : g_v;
#pragma unroll
    for (int mf = 0; mf < 2; mf++) {
        int m0 = rowBlock + wm * 32 + mf * 16 + (lane >> 2);
#pragma unroll
        for (int h8 = 0; h8 < 2; h8++) {
            int m = m0 + h8 * 8;
            int b = m >> 10, s = m & 1023;
            float* base = &dst[(((size_t)(b * NH + head)) * S_ + s) * HD];
#pragma unroll
            for (int nf = 0; nf < 8; nf++) {
                float2 st = make_float2(c[mf][nf][h8 * 2], c[mf][nf][h8 * 2 + 1]);
                *(float2*)&base[nf * 8 + (lane & 3) * 2] = st;
            }
        }
    }
}

// ===========================================================================
// rel bias kernels
// ===========================================================================
__global__ __launch_bounds__(256) void k_relh(const float* __restrict__ RH) {
    const int h = blockIdx.x, bh = blockIdx.y;
    __shared__ float Qs[32][HD + 1], Rs[32][HD + 1];
    const int tid = threadIdx.x;
#pragma unroll
    for (int i = 0; i < 8; i++) {
        int idx = tid + i * 256;
        int r = idx >> 6, c = idx & 63;
        Qs[r][c] = g_q[((size_t)bh * S_ + h * 32 + r) * HD + c];
        Rs[r][c] = RH[(h - r + 31) * HD + c];
    }
    __syncthreads();
    for (int e = tid; e < 1024; e += 256) {
        int w = e >> 5, kh = e & 31;
        float acc = 0.f;
#pragma unroll
        for (int c = 0; c < HD; c++) acc += Qs[w][c] * Rs[kh][c];
        g_relh[((size_t)bh * S_ + h * 32 + w) * 32 + kh] = acc;
    }
}
__global__ __launch_bounds__(256) void k_relw(const float* __restrict__ RW) {
    const int w = blockIdx.x, bh = blockIdx.y;
    __shared__ float Qs[32][HD + 1], Rs[32][HD + 1];
    const int tid = threadIdx.x;
#pragma unroll
    for (int i = 0; i < 8; i++) {
        int idx = tid + i * 256;
        int r = idx >> 6, c = idx & 63;
        Qs[r][c] = g_q[((size_t)bh * S_ + r * 32 + w) * HD + c];
        Rs[r][c] = RW[(w - r + 31) * HD + c];
    }
    __syncthreads();
    for (int e = tid; e < 1024; e += 256) {
        int hh = e >> 5, kw = e & 31;
        float acc = 0.f;
#pragma unroll
        for (int c = 0; c < HD; c++) acc += Qs[hh][c] * Rs[kw][c];
        g_relw[((size_t)bh * S_ + hh * 32 + w) * 32 + kw] = acc;
    }
}

// ===========================================================================
// 2) FLASH: att = softmax(SCALE*q@k^T + bias) @ v   (fused, no scores tensor)
//    one block = 128 q-rows of one bh; 8 warps, each owns 16 rows.
// ===========================================================================
#define QS 72     // Q/K SMEM row stride (bf16)
#define VS 136    // V^T SMEM row stride (bf16)
#define FLASH_SMEM ((4 * 128 * QS + 2 * 64 * VS) * 2)   // 108544 bytes

__global__ __launch_bounds__(256) void k_flash() {
    extern __shared__ __nv_bfloat16 sm[];
    __nv_bfloat16* QH = sm;
    __nv_bfloat16* QL = sm + 128 * QS;
    __nv_bfloat16* KH = sm + 2 * 128 * QS;
    __nv_bfloat16* KL = sm + 3 * 128 * QS;
    __nv_bfloat16* VH = sm + 4 * 128 * QS;
    __nv_bfloat16* VL = sm + 4 * 128 * QS + 64 * VS;

    const int tid = threadIdx.x, lane = tid & 31, warp = tid >> 5;
    const int bh = blockIdx.y;
    const int rowBlock = blockIdx.x * 128;
    const float* __restrict__ Q = g_q + (size_t)bh * S_ * HD;
    const float* __restrict__ K = g_k + (size_t)bh * S_ * HD;
    const float* __restrict__ V = g_v + (size_t)bh * S_ * HD;
    const int r0 = lane >> 2;
    const int qBase = rowBlock + warp * 16;

    // load Q tile hi/lo (persistent)
#pragma unroll
    for (int i = 0; i < 8; i++) {
        int f4 = tid + i * 256;
        int r = f4 >> 4, c = (f4 & 15) * 4;
        float4 v = *(const float4*)&Q[(size_t)(rowBlock + r) * HD + c];
        cvtst4(&QH[r * QS + c], &QL[r * QS + c], v);
    }

    // preload rel_w values (constant across K-tiles)
    float rwv[2][4][2];
#pragma unroll
    for (int h8 = 0; h8 < 2; h8++) {
        int q = qBase + r0 + h8 * 8;
        const float* rw = g_relw + ((size_t)bh * S_ + q) * 32;
#pragma unroll
        for (int t = 0; t < 4; t++) {
            rwv[h8][t][0] = rw[t * 8 + (lane & 3) * 2];
            rwv[h8][t][1] = rw[t * 8 + (lane & 3) * 2 + 1];
        }
    }

    float mcur[2] = {-1e30f, -1e30f};
    float lsum[2] = {0.f, 0.f};
    float o[8][4] = {};

    for (int kt = 0; kt < 8; kt++) {
        __syncthreads();
        // K tile (K-major natural) hi/lo
#pragma unroll
        for (int i = 0; i < 8; i++) {
            int f4 = tid + i * 256;
            int r = f4 >> 4, c = (f4 & 15) * 4;
            float4 v = *(const float4*)&K[(size_t)(kt * 128 + r) * HD + c];
            cvtst4(&KH[r * QS + c], &KL[r * QS + c], v);
        }
        // V tile transposed [d][s] hi/lo
#pragma unroll
        for (int i = 0; i < 32; i++) {
            int idx = tid + i * 256;
            int ks = idx >> 6, d = idx & 63;
            float v = V[(size_t)(kt * 128 + ks) * HD + d];
            __nv_bfloat16 h = __float2bfloat16(v);
            VH[d * VS + ks] = h;
            VL[d * VS + ks] = __float2bfloat16(v - __bfloat162float(h));
        }
        __syncthreads();

        // ---- S = Q K^T (split bf16) ----
        float s[16][4] = {};
#pragma unroll
        for (int kk = 0; kk < 64; kk += 16) {
            uint32_t ah[4], al[4];
            LDSM4(ah, A_ADDRP(QH, QS, warp * 16, kk));
            LDSM4(al, A_ADDRP(QL, QS, warp * 16, kk));
#pragma unroll
            for (int p = 0; p < 8; p++) {
                uint32_t bhf[4], blf[4];
                LDSM4(bhf, B_ADDRP(KH, QS, p * 16, kk));
                LDSM4(blf, B_ADDRP(KL, QS, p * 16, kk));
#pragma unroll
                for (int nt = 0; nt < 2; nt++) {
                    float* cc_ = s[p * 2 + nt];
                    mma16816(cc_, ah, bhf + nt * 2);
                    mma16816(cc_, ah, blf + nt * 2);
                    mma16816(cc_, al, bhf + nt * 2);
                }
            }
        }

        // ---- bias + online softmax ----
        float rhv[2][4];
#pragma unroll
        for (int h8 = 0; h8 < 2; h8++) {
            int q = qBase + r0 + h8 * 8;
            const float* rh = g_relh + ((size_t)bh * S_ + q) * 32 + kt * 4;
#pragma unroll
            for (int t = 0; t < 4; t++) rhv[h8][t] = rh[t];
        }
        float mnew[2] = {mcur[0], mcur[1]};
#pragma unroll
        for (int nf = 0; nf < 16; nf++)
#pragma unroll
            for (int h8 = 0; h8 < 2; h8++)
#pragma unroll
                for (int j = 0; j < 2; j++) {
                    float val = SCALE * s[nf][h8 * 2 + j] + rhv[h8][nf >> 2] + rwv[h8][nf & 3][j];
                    s[nf][h8 * 2 + j] = val;
                    mnew[h8] = fmaxf(mnew[h8], val);
                }
#pragma unroll
        for (int h8 = 0; h8 < 2; h8++) {
            mnew[h8] = fmaxf(mnew[h8], __shfl_xor_sync(0xffffffffu, mnew[h8], 1));
            mnew[h8] = fmaxf(mnew[h8], __shfl_xor_sync(0xffffffffu, mnew[h8], 2));
        }
        float alpha[2], rs[2] = {0.f, 0.f};
#pragma unroll
        for (int h8 = 0; h8 < 2; h8++) { alpha[h8] = __expf(mcur[h8] - mnew[h8]); mcur[h8] = mnew[h8]; }
#pragma unroll
        for (int nf = 0; nf < 16; nf++)
#pragma unroll
            for (int h8 = 0; h8 < 2; h8++)
#pragma unroll
                for (int j = 0; j < 2; j++) {
                    float p = __expf(s[nf][h8 * 2 + j] - mnew[h8]);
                    s[nf][h8 * 2 + j] = p;
                    rs[h8] += p;
                }
#pragma unroll
        for (int h8 = 0; h8 < 2; h8++) {
            rs[h8] += __shfl_xor_sync(0xffffffffu, rs[h8], 1);
            rs[h8] += __shfl_xor_sync(0xffffffffu, rs[h8], 2);
            lsum[h8] = lsum[h8] * alpha[h8] + rs[h8];
        }
#pragma unroll
        for (int nf = 0; nf < 8; nf++) {
            o[nf][0] *= alpha[0]; o[nf][1] *= alpha[0];
            o[nf][2] *= alpha[1]; o[nf][3] *= alpha[1];
        }

        // ---- O += P @ V (P from S registers, split) ----
#pragma unroll
        for (int ks = 0; ks < 8; ks++) {
            uint32_t aph[4], apl[4];
            float* p0 = s[2 * ks];
            float* p1 = s[2 * ks + 1];
            {
                __nv_bfloat16 h0 = __float2bfloat16(p0[0]), h1 = __float2bfloat16(p0[1]);
                __nv_bfloat16 h2 = __float2bfloat16(p0[2]), h3 = __float2bfloat16(p0[3]);
                aph[0] = pkbf2(p0[0], p0[1]); aph[1] = pkbf2(p0[2], p0[3]);
                apl[0] = pkbf2(p0[0] - __bfloat162float(h0), p0[1] - __bfloat162float(h1));
                apl[1] = pkbf2(p0[2] - __bfloat162float(h2), p0[3] - __bfloat162float(h3));
                __nv_bfloat16 g0 = __float2bfloat16(p1[0]), g1 = __float2bfloat16(p1[1]);
                __nv_bfloat16 g2 = __float2bfloat16(p1[2]), g3 = __float2bfloat16(p1[3]);
                aph[2] = pkbf2(p1[0], p1[1]); aph[3] = pkbf2(p1[2], p1[3]);
                apl[2] = pkbf2(p1[0] - __bfloat162float(g0), p1[1] - __bfloat162float(g1));
                apl[3] = pkbf2(p1[2] - __bfloat162float(g2), p1[3] - __bfloat162float(g3));
            }
#pragma unroll
            for (int dp = 0; dp < 4; dp++) {
                uint32_t vh[4], vl[4];
                LDSM4(vh, B_ADDRP(VH, VS, dp * 16, ks * 16));
                LDSM4(vl, B_ADDRP(VL, VS, dp * 16, ks * 16));
#pragma unroll
                for (int nt = 0; nt < 2; nt++) {
                    float* cc_ = o[dp * 2 + nt];
                    mma16816(cc_, aph, vh + nt * 2);
                    mma16816(cc_, aph, vl + nt * 2);
                    mma16816(cc_, apl, vh + nt * 2);
                }
            }
        }
    }

    // epilogue: O /= l
    float inv[2] = {1.f / lsum[0], 1.f / lsum[1]};
    float* O = g_att + (size_t)bh * S_ * HD;
#pragma unroll
    for (int h8 = 0; h8 < 2; h8++) {
        int q = qBase + r0 + h8 * 8;
#pragma unroll
        for (int nf = 0; nf < 8; nf++) {
            float2 st = make_float2(o[nf][h8 * 2] * inv[h8], o[nf][h8 * 2 + 1] * inv[h8]);
            *(float2*)&O[(size_t)q * HD + nf * 8 + (lane & 3) * 2] = st;
        }
    }
}

// ===========================================================================
// 3) out = gather(att) @ Wproj + bproj  (4096x768, K=768)
// ===========================================================================
__global__ __launch_bounds__(256) void k_proj(const float* __restrict__ Wp,
                                              const float* __restrict__ bp,
                                              float* __restrict__ out) {
    __shared__ __align__(16) __nv_bfloat16 Ah[128][40], Al[128][40];
    __shared__ __align__(16) __nv_bfloat16 Bh[128][40], Bl[128][40];
    const int tid = threadIdx.x, lane = tid & 31, warp = tid >> 5;
    const int wm = warp & 3, wn = warp >> 2;
    const int rowBlock = blockIdx.y * 128, colBlock = blockIdx.x * 128;
    float c[2][8][4] = {};

    for (int kt = 0; kt < C_; kt += 32) {
#pragma unroll
        for (int i = 0; i < 4; i++) {
            int f4 = tid + i * 256;
            int r = f4 >> 3, cc = (f4 & 7) * 4;
            int row = rowBlock + r;
            int b = row >> 10, s = row & 1023;
            int k = kt + cc;
            int head = k >> 6, d = k & 63;
            float4 v = *(const float4*)&g_att[(((size_t)(b * NH + head)) * S_ + s) * HD + d];
            cvtst4(&Ah[r][cc], &Al[r][cc], v);
        }
#pragma unroll
        for (int i = 0; i < 16; i++) {
            int idx = tid + i * 256;
            int k = idx >> 7, n = idx & 127;
            float v = Wp[(size_t)(kt + k) * C_ + colBlock + n];
            __nv_bfloat16 h = __float2bfloat16(v);
            Bh[n][k] = h;
            Bl[n][k] = __float2bfloat16(v - __bfloat162float(h));
        }
        __syncthreads();
#pragma unroll
        for (int kk = 0; kk < 32; kk += 16) {
            uint32_t ah[2][4], al[2][4];
#pragma unroll
            for (int mf = 0; mf < 2; mf++) {
                LDSM4(ah[mf], A_ADDR(Ah, wm * 32 + mf * 16, kk));
                LDSM4(al[mf], A_ADDR(Al, wm * 32 + mf * 16, kk));
            }
#pragma unroll
            for (int p = 0; p < 4; p++) {
                uint32_t bhf[4], blf[4];
                LDSM4(bhf, B_ADDR(Bh, wn * 64 + p * 16, kk));
                LDSM4(blf, B_ADDR(Bl, wn * 64 + p * 16, kk));
#pragma unroll
                for (int mf = 0; mf < 2; mf++)
#pragma unroll
                    for (int nt = 0; nt < 2; nt++) {
                        float* cc_ = c[mf][p * 2 + nt];
                        mma16816(cc_, ah[mf], bhf + nt * 2);
                        mma16816(cc_, ah[mf], blf + nt * 2);
                        mma16816(cc_, al[mf], bhf + nt * 2);
                    }
            }
        }
        __syncthreads();
    }
    const int col0 = colBlock + wn * 64;
#pragma unroll
    for (int mf = 0; mf < 2; mf++) {
        int m0 = rowBlock + wm * 32 + mf * 16 + (lane >> 2);
#pragma unroll
        for (int h8 = 0; h8 < 2; h8++) {
            int m = m0 + h8 * 8;
#pragma unroll
            for (int nf = 0; nf < 8; nf++) {
                int n = col0 + nf * 8 + (lane & 3) * 2;
                float2 bv = *(const float2*)&bp[n];
                float2 st = make_float2(c[mf][nf][h8 * 2] + bv.x, c[mf][nf][h8 * 2 + 1] + bv.y);
                *(float2*)&out[(size_t)m * C_ + n] = st;
            }
        }
    }
}

// ---------------------------------------------------------------------------
extern "C" void kernel_launch(void* const* d_in, const int* in_sizes, int n_in,
                              void* d_out, int out_size) {
    const float* x     = (const float*)d_in[0];
    const float* Wqkv  = (const float*)d_in[1];
    const float* Wproj = (const float*)d_in[2];
    const float* bproj = (const float*)d_in[3];
    const float* rph   = (const float*)d_in[4];
    const float* rpw   = (const float*)d_in[5];
    float* out = (float*)d_out;

    static int smem_set = 0;
    if (!smem_set) {
        cudaFuncSetAttribute(k_flash, cudaFuncAttributeMaxDynamicSharedMemorySize, FLASH_SMEM);
        smem_set = 1;
    }

    k_qkv<<<dim3(C3 / 128, (B_ * S_) / 128), 256>>>(x, Wqkv);
    k_relh<<<dim3(32, BH), 256>>>(rph);
    k_relw<<<dim3(32, BH), 256>>>(rpw);
    k_flash<<<dim3(S_ / 128, BH), 256, FLASH_SMEM>>>();
    k_proj<<<dim3(C_ / 128, (B_ * S_) / 128), 256>>>(Wproj, bproj, out);
}

// round 11
// speedup vs baseline: 2.3176x; 1.0268x over previous
#include <cuda_runtime.h>
#include <cuda_bf16.h>
#include <cstdint>
#include <math.h>

// Problem constants
#define B_    4
#define NH    12
#define BH    48
#define S_    1024
#define HD    64
#define C_    768
#define C3    2304
#define SCALE 0.125f

// ---------------- scratch ----------------
__device__ float g_q[BH * S_ * HD];
__device__ float g_k[BH * S_ * HD];
__device__ float g_v[BH * S_ * HD];
__device__ float g_relh[BH * S_ * 32];
__device__ float g_relw[BH * S_ * 32];
__device__ float g_att[BH * S_ * HD];

// ---------------- mma.sync helpers ----------------
__device__ __forceinline__ uint32_t smem_u32(const void* p) {
    uint32_t a;
    asm("{ .reg .u64 t; cvta.to.shared.u64 t, %1; cvt.u32.u64 %0, t; }" : "=r"(a) : "l"(p));
    return a;
}

#define LDSM4(r, addr) \
    asm volatile("ldmatrix.sync.aligned.m8n8.x4.shared.b16 {%0,%1,%2,%3}, [%4];" \
        : "=r"((r)[0]), "=r"((r)[1]), "=r"((r)[2]), "=r"((r)[3]) : "r"(addr))

__device__ __forceinline__ void mma16816(float* c, const uint32_t* a, const uint32_t* b) {
    asm volatile("mma.sync.aligned.m16n8k16.row.col.f32.bf16.bf16.f32 "
        "{%0,%1,%2,%3}, {%4,%5,%6,%7}, {%8,%9}, {%0,%1,%2,%3};"
        : "+f"(c[0]), "+f"(c[1]), "+f"(c[2]), "+f"(c[3])
        : "r"(a[0]), "r"(a[1]), "r"(a[2]), "r"(a[3]), "r"(b[0]), "r"(b[1]));
}

__device__ __forceinline__ uint32_t pkbf2(float x, float y) {
    __nv_bfloat162 t = __halves2bfloat162(__float2bfloat16(x), __float2bfloat16(y));
    return *reinterpret_cast<uint32_t*>(&t);
}

// float4 -> bf16 hi/lo at K-major slot (8B each)
__device__ __forceinline__ void cvtst4(__nv_bfloat16* ph, __nv_bfloat16* pl, float4 v) {
    __nv_bfloat16 h0 = __float2bfloat16(v.x), h1 = __float2bfloat16(v.y);
    __nv_bfloat16 h2 = __float2bfloat16(v.z), h3 = __float2bfloat16(v.w);
    __nv_bfloat162 H0 = __halves2bfloat162(h0, h1), H1 = __halves2bfloat162(h2, h3);
    *(uint2*)ph = make_uint2(*(uint32_t*)&H0, *(uint32_t*)&H1);
    __nv_bfloat162 L0 = __halves2bfloat162(__float2bfloat16(v.x - __bfloat162float(h0)),
                                           __float2bfloat16(v.y - __bfloat162float(h1)));
    __nv_bfloat162 L1 = __halves2bfloat162(__float2bfloat16(v.z - __bfloat162float(h2)),
                                           __float2bfloat16(v.w - __bfloat162float(h3)));
    *(uint2*)pl = make_uint2(*(uint32_t*)&L0, *(uint32_t*)&L1);
}

// fragment address helpers
#define A_ADDR(T, mBase, kk) smem_u32(&(T)[(mBase) + (lane & 15)][(kk) + (lane >> 4) * 8])
#define B_ADDR(T, nBase, kk) \
    smem_u32(&(T)[(nBase) + (lane & 7) + ((lane >> 4) & 1) * 8][(kk) + ((lane >> 3) & 1) * 8])
#define A_ADDRP(P, st, mBase, kk) smem_u32((P) + ((mBase) + (lane & 15)) * (st) + (kk) + (lane >> 4) * 8)
#define B_ADDRP(P, st, nBase, kk) \
    smem_u32((P) + ((nBase) + (lane & 7) + ((lane >> 4) & 1) * 8) * (st) + (kk) + ((lane >> 3) & 1) * 8)

// ===========================================================================
// 1) qkv = x @ Wqkv (4096x2304, K=768) -> scatter q/k/v
// ===========================================================================
__global__ __launch_bounds__(256) void k_qkv(const float* __restrict__ X,
                                             const float* __restrict__ W) {
    __shared__ __align__(16) __nv_bfloat16 Ah[128][40], Al[128][40];
    __shared__ __align__(16) __nv_bfloat16 Bh[128][40], Bl[128][40];
    const int tid = threadIdx.x, lane = tid & 31, warp = tid >> 5;
    const int wm = warp & 3, wn = warp >> 2;
    const int rowBlock = blockIdx.y * 128, colBlock = blockIdx.x * 128;
    float c[2][8][4] = {};

    for (int kt = 0; kt < C_; kt += 32) {
#pragma unroll
        for (int i = 0; i < 4; i++) {
            int f4 = tid + i * 256;
            int r = f4 >> 3, cc = (f4 & 7) * 4;
            float4 v = *(const float4*)&X[(size_t)(rowBlock + r) * C_ + kt + cc];
            cvtst4(&Ah[r][cc], &Al[r][cc], v);
        }
#pragma unroll
        for (int i = 0; i < 16; i++) {
            int idx = tid + i * 256;
            int k = idx >> 7, n = idx & 127;
            float v = W[(size_t)(kt + k) * C3 + colBlock + n];
            __nv_bfloat16 h = __float2bfloat16(v);
            Bh[n][k] = h;
            Bl[n][k] = __float2bfloat16(v - __bfloat162float(h));
        }
        __syncthreads();
#pragma unroll
        for (int kk = 0; kk < 32; kk += 16) {
            uint32_t ah[2][4], al[2][4];
#pragma unroll
            for (int mf = 0; mf < 2; mf++) {
                LDSM4(ah[mf], A_ADDR(Ah, wm * 32 + mf * 16, kk));
                LDSM4(al[mf], A_ADDR(Al, wm * 32 + mf * 16, kk));
            }
#pragma unroll
            for (int p = 0; p < 4; p++) {
                uint32_t bhf[4], blf[4];
                LDSM4(bhf, B_ADDR(Bh, wn * 64 + p * 16, kk));
                LDSM4(blf, B_ADDR(Bl, wn * 64 + p * 16, kk));
#pragma unroll
                for (int mf = 0; mf < 2; mf++)
#pragma unroll
                    for (int nt = 0; nt < 2; nt++) {
                        float* cc_ = c[mf][p * 2 + nt];
                        mma16816(cc_, ah[mf], bhf + nt * 2);
                        mma16816(cc_, ah[mf], blf + nt * 2);
                        mma16816(cc_, al[mf], bhf + nt * 2);
                    }
            }
        }
        __syncthreads();
    }
    const int col0 = colBlock + wn * 64;
    const int part = col0 / C_;
    const int rem = col0 - part * C_;
    const int head = rem >> 6;
    float* dst = (part == 0) ? g_q : (part == 1) ? g_k : g_v;
#pragma unroll
    for (int mf = 0; mf < 2; mf++) {
        int m0 = rowBlock + wm * 32 + mf * 16 + (lane >> 2);
#pragma unroll
        for (int h8 = 0; h8 < 2; h8++) {
            int m = m0 + h8 * 8;
            int b = m >> 10, s = m & 1023;
            float* base = &dst[(((size_t)(b * NH + head)) * S_ + s) * HD];
#pragma unroll
            for (int nf = 0; nf < 8; nf++) {
                float2 st = make_float2(c[mf][nf][h8 * 2], c[mf][nf][h8 * 2 + 1]);
                *(float2*)&base[nf * 8 + (lane & 3) * 2] = st;
            }
        }
    }
}

// ===========================================================================
// rel bias kernels
// ===========================================================================
__global__ __launch_bounds__(256) void k_relh(const float* __restrict__ RH) {
    const int h = blockIdx.x, bh = blockIdx.y;
    __shared__ float Qs[32][HD + 1], Rs[32][HD + 1];
    const int tid = threadIdx.x;
#pragma unroll
    for (int i = 0; i < 8; i++) {
        int idx = tid + i * 256;
        int r = idx >> 6, c = idx & 63;
        Qs[r][c] = g_q[((size_t)bh * S_ + h * 32 + r) * HD + c];
        Rs[r][c] = RH[(h - r + 31) * HD + c];
    }
    __syncthreads();
    for (int e = tid; e < 1024; e += 256) {
        int w = e >> 5, kh = e & 31;
        float acc = 0.f;
#pragma unroll
        for (int c = 0; c < HD; c++) acc += Qs[w][c] * Rs[kh][c];
        g_relh[((size_t)bh * S_ + h * 32 + w) * 32 + kh] = acc;
    }
}
__global__ __launch_bounds__(256) void k_relw(const float* __restrict__ RW) {
    const int w = blockIdx.x, bh = blockIdx.y;
    __shared__ float Qs[32][HD + 1], Rs[32][HD + 1];
    const int tid = threadIdx.x;
#pragma unroll
    for (int i = 0; i < 8; i++) {
        int idx = tid + i * 256;
        int r = idx >> 6, c = idx & 63;
        Qs[r][c] = g_q[((size_t)bh * S_ + r * 32 + w) * HD + c];
        Rs[r][c] = RW[(w - r + 31) * HD + c];
    }
    __syncthreads();
    for (int e = tid; e < 1024; e += 256) {
        int hh = e >> 5, kw = e & 31;
        float acc = 0.f;
#pragma unroll
        for (int c = 0; c < HD; c++) acc += Qs[hh][c] * Rs[kw][c];
        g_relw[((size_t)bh * S_ + hh * 32 + w) * 32 + kw] = acc;
    }
}

// ===========================================================================
// 2) FLASH: 64-key tiles, 16 iterations, <=128 regs, 2 CTAs/SM
// ===========================================================================
#define QS 72     // Q/K SMEM row stride (bf16)
#define VS 72     // V^T SMEM row stride (bf16)
#define KT_ 64    // keys per tile
#define FLASH_SMEM ((2 * 128 * QS + 2 * 64 * QS + 2 * 64 * VS) * 2)  // 73728 B

__global__ __launch_bounds__(256, 2) void k_flash() {
    extern __shared__ __nv_bfloat16 sm[];
    __nv_bfloat16* QH = sm;
    __nv_bfloat16* QL = sm + 128 * QS;
    __nv_bfloat16* KH = sm + 2 * 128 * QS;
    __nv_bfloat16* KL = sm + 2 * 128 * QS + 64 * QS;
    __nv_bfloat16* VH = sm + 2 * 128 * QS + 2 * 64 * QS;
    __nv_bfloat16* VL = sm + 2 * 128 * QS + 2 * 64 * QS + 64 * VS;

    const int tid = threadIdx.x, lane = tid & 31, warp = tid >> 5;
    const int bh = blockIdx.y;
    const int rowBlock = blockIdx.x * 128;
    const float* __restrict__ Q = g_q + (size_t)bh * S_ * HD;
    const float* __restrict__ K = g_k + (size_t)bh * S_ * HD;
    const float* __restrict__ V = g_v + (size_t)bh * S_ * HD;
    const int r0 = lane >> 2;
    const int qBase = rowBlock + warp * 16;

    // persistent Q tile hi/lo
#pragma unroll
    for (int i = 0; i < 8; i++) {
        int f4 = tid + i * 256;
        int r = f4 >> 4, c = (f4 & 15) * 4;
        float4 v = *(const float4*)&Q[(size_t)(rowBlock + r) * HD + c];
        cvtst4(&QH[r * QS + c], &QL[r * QS + c], v);
    }

    // rel_w values (constant across K-tiles): kw = (nf&3)*8 + (lane&3)*2 + j
    float rwv[2][4][2];
#pragma unroll
    for (int h8 = 0; h8 < 2; h8++) {
        int q = qBase + r0 + h8 * 8;
        const float* rw = g_relw + ((size_t)bh * S_ + q) * 32;
#pragma unroll
        for (int t = 0; t < 4; t++) {
            rwv[h8][t][0] = rw[t * 8 + (lane & 3) * 2];
            rwv[h8][t][1] = rw[t * 8 + (lane & 3) * 2 + 1];
        }
    }

    float mcur[2] = {-1e30f, -1e30f};
    float lsum[2] = {0.f, 0.f};
    float o[8][4] = {};

    for (int kt = 0; kt < 16; kt++) {
        __syncthreads();
        // K tile: 64 keys x 64 d (K-major natural), hi/lo
#pragma unroll
        for (int i = 0; i < 4; i++) {
            int f4 = tid + i * 256;
            int r = f4 >> 4, c = (f4 & 15) * 4;
            float4 v = *(const float4*)&K[(size_t)(kt * KT_ + r) * HD + c];
            cvtst4(&KH[r * QS + c], &KL[r * QS + c], v);
        }
        // V tile transposed [d][s], hi/lo (64x64)
#pragma unroll
        for (int i = 0; i < 16; i++) {
            int idx = tid + i * 256;
            int ks = idx >> 6, d = idx & 63;
            float v = V[(size_t)(kt * KT_ + ks) * HD + d];
            __nv_bfloat16 h = __float2bfloat16(v);
            VH[d * VS + ks] = h;
            VL[d * VS + ks] = __float2bfloat16(v - __bfloat162float(h));
        }
        __syncthreads();

        // ---- S = Q K^T over 64 keys ----
        float s[8][4] = {};
#pragma unroll
        for (int kk = 0; kk < 64; kk += 16) {
            uint32_t ah[4], al[4];
            LDSM4(ah, A_ADDRP(QH, QS, warp * 16, kk));
            LDSM4(al, A_ADDRP(QL, QS, warp * 16, kk));
#pragma unroll
            for (int p = 0; p < 4; p++) {
                uint32_t bhf[4], blf[4];
                LDSM4(bhf, B_ADDRP(KH, QS, p * 16, kk));
                LDSM4(blf, B_ADDRP(KL, QS, p * 16, kk));
#pragma unroll
                for (int nt = 0; nt < 2; nt++) {
                    float* cc_ = s[p * 2 + nt];
                    mma16816(cc_, ah, bhf + nt * 2);
                    mma16816(cc_, ah, blf + nt * 2);
                    mma16816(cc_, al, bhf + nt * 2);
                }
            }
        }

        // ---- bias + online softmax (kh = kt*2 + (nf>>2)) ----
        float rhv[2][2];
#pragma unroll
        for (int h8 = 0; h8 < 2; h8++) {
            int q = qBase + r0 + h8 * 8;
            const float* rh = g_relh + ((size_t)bh * S_ + q) * 32 + kt * 2;
            rhv[h8][0] = rh[0];
            rhv[h8][1] = rh[1];
        }
        float mnew[2] = {mcur[0], mcur[1]};
#pragma unroll
        for (int nf = 0; nf < 8; nf++)
#pragma unroll
            for (int h8 = 0; h8 < 2; h8++)
#pragma unroll
                for (int j = 0; j < 2; j++) {
                    float val = SCALE * s[nf][h8 * 2 + j] + rhv[h8][nf >> 2] + rwv[h8][nf & 3][j];
                    s[nf][h8 * 2 + j] = val;
                    mnew[h8] = fmaxf(mnew[h8], val);
                }
#pragma unroll
        for (int h8 = 0; h8 < 2; h8++) {
            mnew[h8] = fmaxf(mnew[h8], __shfl_xor_sync(0xffffffffu, mnew[h8], 1));
            mnew[h8] = fmaxf(mnew[h8], __shfl_xor_sync(0xffffffffu, mnew[h8], 2));
        }
        float alpha[2], rs[2] = {0.f, 0.f};
#pragma unroll
        for (int h8 = 0; h8 < 2; h8++) { alpha[h8] = __expf(mcur[h8] - mnew[h8]); mcur[h8] = mnew[h8]; }
#pragma unroll
        for (int nf = 0; nf < 8; nf++)
#pragma unroll
            for (int h8 = 0; h8 < 2; h8++)
#pragma unroll
                for (int j = 0; j < 2; j++) {
                    float p = __expf(s[nf][h8 * 2 + j] - mnew[h8]);
                    s[nf][h8 * 2 + j] = p;
                    rs[h8] += p;
                }
#pragma unroll
        for (int h8 = 0; h8 < 2; h8++) {
            rs[h8] += __shfl_xor_sync(0xffffffffu, rs[h8], 1);
            rs[h8] += __shfl_xor_sync(0xffffffffu, rs[h8], 2);
            lsum[h8] = lsum[h8] * alpha[h8] + rs[h8];
        }
#pragma unroll
        for (int nf = 0; nf < 8; nf++) {
            o[nf][0] *= alpha[0]; o[nf][1] *= alpha[0];
            o[nf][2] *= alpha[1]; o[nf][3] *= alpha[1];
        }

        // ---- O += P @ V (P from S registers, hi/lo split) ----
#pragma unroll
        for (int ks = 0; ks < 4; ks++) {
            uint32_t aph[4], apl[4];
            float* p0 = s[2 * ks];
            float* p1 = s[2 * ks + 1];
            {
                __nv_bfloat16 h0 = __float2bfloat16(p0[0]), h1 = __float2bfloat16(p0[1]);
                __nv_bfloat16 h2 = __float2bfloat16(p0[2]), h3 = __float2bfloat16(p0[3]);
                aph[0] = pkbf2(p0[0], p0[1]); aph[1] = pkbf2(p0[2], p0[3]);
                apl[0] = pkbf2(p0[0] - __bfloat162float(h0), p0[1] - __bfloat162float(h1));
                apl[1] = pkbf2(p0[2] - __bfloat162float(h2), p0[3] - __bfloat162float(h3));
                __nv_bfloat16 g0 = __float2bfloat16(p1[0]), g1 = __float2bfloat16(p1[1]);
                __nv_bfloat16 g2 = __float2bfloat16(p1[2]), g3 = __float2bfloat16(p1[3]);
                aph[2] = pkbf2(p1[0], p1[1]); aph[3] = pkbf2(p1[2], p1[3]);
                apl[2] = pkbf2(p1[0] - __bfloat162float(g0), p1[1] - __bfloat162float(g1));
                apl[3] = pkbf2(p1[2] - __bfloat162float(g2), p1[3] - __bfloat162float(g3));
            }
#pragma unroll
            for (int dp = 0; dp < 4; dp++) {
                uint32_t vh[4], vl[4];
                LDSM4(vh, B_ADDRP(VH, VS, dp * 16, ks * 16));
                LDSM4(vl, B_ADDRP(VL, VS, dp * 16, ks * 16));
#pragma unroll
                for (int nt = 0; nt < 2; nt++) {
                    float* cc_ = o[dp * 2 + nt];
                    mma16816(cc_, aph, vh + nt * 2);
                    mma16816(cc_, aph, vl + nt * 2);
                    mma16816(cc_, apl, vh + nt * 2);
                }
            }
        }
    }

    // epilogue
    float inv[2] = {1.f / lsum[0], 1.f / lsum[1]};
    float* O = g_att + (size_t)bh * S_ * HD;
#pragma unroll
    for (int h8 = 0; h8 < 2; h8++) {
        int q = qBase + r0 + h8 * 8;
#pragma unroll
        for (int nf = 0; nf < 8; nf++) {
            float2 st = make_float2(o[nf][h8 * 2] * inv[h8], o[nf][h8 * 2 + 1] * inv[h8]);
            *(float2*)&O[(size_t)q * HD + nf * 8 + (lane & 3) * 2] = st;
        }
    }
}

// ===========================================================================
// 3) out = gather(att) @ Wproj + bproj  (4096x768, K=768)
// ===========================================================================
__global__ __launch_bounds__(256) void k_proj(const float* __restrict__ Wp,
                                              const float* __restrict__ bp,
                                              float* __restrict__ out) {
    __shared__ __align__(16) __nv_bfloat16 Ah[128][40], Al[128][40];
    __shared__ __align__(16) __nv_bfloat16 Bh[128][40], Bl[128][40];
    const int tid = threadIdx.x, lane = tid & 31, warp = tid >> 5;
    const int wm = warp & 3, wn = warp >> 2;
    const int rowBlock = blockIdx.y * 128, colBlock = blockIdx.x * 128;
    float c[2][8][4] = {};

    for (int kt = 0; kt < C_; kt += 32) {
#pragma unroll
        for (int i = 0; i < 4; i++) {
            int f4 = tid + i * 256;
            int r = f4 >> 3, cc = (f4 & 7) * 4;
            int row = rowBlock + r;
            int b = row >> 10, s = row & 1023;
            int k = kt + cc;
            int head = k >> 6, d = k & 63;
            float4 v = *(const float4*)&g_att[(((size_t)(b * NH + head)) * S_ + s) * HD + d];
            cvtst4(&Ah[r][cc], &Al[r][cc], v);
        }
#pragma unroll
        for (int i = 0; i < 16; i++) {
            int idx = tid + i * 256;
            int k = idx >> 7, n = idx & 127;
            float v = Wp[(size_t)(kt + k) * C_ + colBlock + n];
            __nv_bfloat16 h = __float2bfloat16(v);
            Bh[n][k] = h;
            Bl[n][k] = __float2bfloat16(v - __bfloat162float(h));
        }
        __syncthreads();
#pragma unroll
        for (int kk = 0; kk < 32; kk += 16) {
            uint32_t ah[2][4], al[2][4];
#pragma unroll
            for (int mf = 0; mf < 2; mf++) {
                LDSM4(ah[mf], A_ADDR(Ah, wm * 32 + mf * 16, kk));
                LDSM4(al[mf], A_ADDR(Al, wm * 32 + mf * 16, kk));
            }
#pragma unroll
            for (int p = 0; p < 4; p++) {
                uint32_t bhf[4], blf[4];
                LDSM4(bhf, B_ADDR(Bh, wn * 64 + p * 16, kk));
                LDSM4(blf, B_ADDR(Bl, wn * 64 + p * 16, kk));
#pragma unroll
                for (int mf = 0; mf < 2; mf++)
#pragma unroll
                    for (int nt = 0; nt < 2; nt++) {
                        float* cc_ = c[mf][p * 2 + nt];
                        mma16816(cc_, ah[mf], bhf + nt * 2);
                        mma16816(cc_, ah[mf], blf + nt * 2);
                        mma16816(cc_, al[mf], bhf + nt * 2);
                    }
            }
        }
        __syncthreads();
    }
    const int col0 = colBlock + wn * 64;
#pragma unroll
    for (int mf = 0; mf < 2; mf++) {
        int m0 = rowBlock + wm * 32 + mf * 16 + (lane >> 2);
#pragma unroll
        for (int h8 = 0; h8 < 2; h8++) {
            int m = m0 + h8 * 8;
#pragma unroll
            for (int nf = 0; nf < 8; nf++) {
                int n = col0 + nf * 8 + (lane & 3) * 2;
                float2 bv = *(const float2*)&bp[n];
                float2 st = make_float2(c[mf][nf][h8 * 2] + bv.x, c[mf][nf][h8 * 2 + 1] + bv.y);
                *(float2*)&out[(size_t)m * C_ + n] = st;
            }
        }
    }
}

// ---------------------------------------------------------------------------
extern "C" void kernel_launch(void* const* d_in, const int* in_sizes, int n_in,
                              void* d_out, int out_size) {
    const float* x     = (const float*)d_in[0];
    const float* Wqkv  = (const float*)d_in[1];
    const float* Wproj = (const float*)d_in[2];
    const float* bproj = (const float*)d_in[3];
    const float* rph   = (const float*)d_in[4];
    const float* rpw   = (const float*)d_in[5];
    float* out = (float*)d_out;

    static int smem_set = 0;
    if (!smem_set) {
        cudaFuncSetAttribute(k_flash, cudaFuncAttributeMaxDynamicSharedMemorySize, FLASH_SMEM);
        smem_set = 1;
    }

    k_qkv<<<dim3(C3 / 128, (B_ * S_) / 128), 256>>>(x, Wqkv);
    k_relh<<<dim3(32, BH), 256>>>(rph);
    k_relw<<<dim3(32, BH), 256>>>(rpw);
    k_flash<<<dim3(S_ / 128, BH), 256, FLASH_SMEM>>>();
    k_proj<<<dim3(C_ / 128, (B_ * S_) / 128), 256>>>(Wproj, bproj, out);
}

// round 17
// speedup vs baseline: 2.4215x; 1.0448x over previous
#include <cuda_runtime.h>
#include <cuda_bf16.h>
#include <cstdint>
#include <math.h>

// Problem constants
#define B_    4
#define NH    12
#define BH    48
#define S_    1024
#define HD    64
#define C_    768
#define C3    2304
#define SCALE 0.125f

// ---------------- scratch ----------------
__device__ float g_q[BH * S_ * HD];
__device__ float g_relh[BH * S_ * 32];
__device__ float g_relw[BH * S_ * 32];
__device__ float g_att[BH * S_ * HD];
// pre-split bf16 K (row-major [s][d]) and V (transposed [d][s])
__device__ __nv_bfloat16 g_kh[BH * S_ * HD], g_kl[BH * S_ * HD];
__device__ __nv_bfloat16 g_vth[BH * HD * S_], g_vtl[BH * HD * S_];

// ---------------- mma.sync helpers ----------------
__device__ __forceinline__ uint32_t smem_u32(const void* p) {
    uint32_t a;
    asm("{ .reg .u64 t; cvta.to.shared.u64 t, %1; cvt.u32.u64 %0, t; }" : "=r"(a) : "l"(p));
    return a;
}

#define LDSM4(r, addr) \
    asm volatile("ldmatrix.sync.aligned.m8n8.x4.shared.b16 {%0,%1,%2,%3}, [%4];" \
        : "=r"((r)[0]), "=r"((r)[1]), "=r"((r)[2]), "=r"((r)[3]) : "r"(addr))

__device__ __forceinline__ void mma16816(float* c, const uint32_t* a, const uint32_t* b) {
    asm volatile("mma.sync.aligned.m16n8k16.row.col.f32.bf16.bf16.f32 "
        "{%0,%1,%2,%3}, {%4,%5,%6,%7}, {%8,%9}, {%0,%1,%2,%3};"
        : "+f"(c[0]), "+f"(c[1]), "+f"(c[2]), "+f"(c[3])
        : "r"(a[0]), "r"(a[1]), "r"(a[2]), "r"(a[3]), "r"(b[0]), "r"(b[1]));
}

__device__ __forceinline__ uint32_t pkbf2(float x, float y) {
    __nv_bfloat162 t = __halves2bfloat162(__float2bfloat16(x), __float2bfloat16(y));
    return *reinterpret_cast<uint32_t*>(&t);
}

#define CP16(dst, src) \
    asm volatile("cp.async.cg.shared.global [%0], [%1], 16;" :: "r"(dst), "l"(src))
#define CP_COMMIT() asm volatile("cp.async.commit_group;")

// float4 -> bf16 hi/lo at K-major slot (8B each)
__device__ __forceinline__ void cvtst4(__nv_bfloat16* ph, __nv_bfloat16* pl, float4 v) {
    __nv_bfloat16 h0 = __float2bfloat16(v.x), h1 = __float2bfloat16(v.y);
    __nv_bfloat16 h2 = __float2bfloat16(v.z), h3 = __float2bfloat16(v.w);
    __nv_bfloat162 H0 = __halves2bfloat162(h0, h1), H1 = __halves2bfloat162(h2, h3);
    *(uint2*)ph = make_uint2(*(uint32_t*)&H0, *(uint32_t*)&H1);
    __nv_bfloat162 L0 = __halves2bfloat162(__float2bfloat16(v.x - __bfloat162float(h0)),
                                           __float2bfloat16(v.y - __bfloat162float(h1)));
    __nv_bfloat162 L1 = __halves2bfloat162(__float2bfloat16(v.z - __bfloat162float(h2)),
                                           __float2bfloat16(v.w - __bfloat162float(h3)));
    *(uint2*)pl = make_uint2(*(uint32_t*)&L0, *(uint32_t*)&L1);
}

// fragment address helpers
#define A_ADDR(T, mBase, kk) smem_u32(&(T)[(mBase) + (lane & 15)][(kk) + (lane >> 4) * 8])
#define B_ADDR(T, nBase, kk) \
    smem_u32(&(T)[(nBase) + (lane & 7) + ((lane >> 4) & 1) * 8][(kk) + ((lane >> 3) & 1) * 8])
#define A_ADDRP(P, st, mBase, kk) smem_u32((P) + ((mBase) + (lane & 15)) * (st) + (kk) + (lane >> 4) * 8)
#define B_ADDRP(P, st, nBase, kk) \
    smem_u32((P) + ((nBase) + (lane & 7) + ((lane >> 4) & 1) * 8) * (st) + (kk) + ((lane >> 3) & 1) * 8)

// ===========================================================================
// 1) qkv = x @ Wqkv -> q fp32, k bf16 hi/lo [s][d], v bf16 hi/lo transposed [d][s]
// ===========================================================================
__global__ __launch_bounds__(256) void k_qkv(const float* __restrict__ X,
                                             const float* __restrict__ W) {
    __shared__ __align__(16) __nv_bfloat16 Ah[128][40], Al[128][40];
    __shared__ __align__(16) __nv_bfloat16 Bh[128][40], Bl[128][40];
    const int tid = threadIdx.x, lane = tid & 31, warp = tid >> 5;
    const int wm = warp & 3, wn = warp >> 2;
    const int rowBlock = blockIdx.y * 128, colBlock = blockIdx.x * 128;
    float c[2][8][4] = {};

    for (int kt = 0; kt < C_; kt += 32) {
#pragma unroll
        for (int i = 0; i < 4; i++) {
            int f4 = tid + i * 256;
            int r = f4 >> 3, cc = (f4 & 7) * 4;
            float4 v = *(const float4*)&X[(size_t)(rowBlock + r) * C_ + kt + cc];
            cvtst4(&Ah[r][cc], &Al[r][cc], v);
        }
#pragma unroll
        for (int i = 0; i < 16; i++) {
            int idx = tid + i * 256;
            int k = idx >> 7, n = idx & 127;
            float v = W[(size_t)(kt + k) * C3 + colBlock + n];
            __nv_bfloat16 h = __float2bfloat16(v);
            Bh[n][k] = h;
            Bl[n][k] = __float2bfloat16(v - __bfloat162float(h));
        }
        __syncthreads();
#pragma unroll
        for (int kk = 0; kk < 32; kk += 16) {
            uint32_t ah[2][4], al[2][4];
#pragma unroll
            for (int mf = 0; mf < 2; mf++) {
                LDSM4(ah[mf], A_ADDR(Ah, wm * 32 + mf * 16, kk));
                LDSM4(al[mf], A_ADDR(Al, wm * 32 + mf * 16, kk));
            }
#pragma unroll
            for (int p = 0; p < 4; p++) {
                uint32_t bhf[4], blf[4];
                LDSM4(bhf, B_ADDR(Bh, wn * 64 + p * 16, kk));
                LDSM4(blf, B_ADDR(Bl, wn * 64 + p * 16, kk));
#pragma unroll
                for (int mf = 0; mf < 2; mf++)
#pragma unroll
                    for (int nt = 0; nt < 2; nt++) {
                        float* cc_ = c[mf][p * 2 + nt];
                        mma16816(cc_, ah[mf], bhf + nt * 2);
                        mma16816(cc_, ah[mf], blf + nt * 2);
                        mma16816(cc_, al[mf], bhf + nt * 2);
                    }
            }
        }
        __syncthreads();
    }
    const int col0 = colBlock + wn * 64;
    const int part = col0 / C_;
    const int head = (col0 - part * C_) >> 6;
#pragma unroll
    for (int mf = 0; mf < 2; mf++) {
        int m0 = rowBlock + wm * 32 + mf * 16 + (lane >> 2);
#pragma unroll
        for (int h8 = 0; h8 < 2; h8++) {
            int m = m0 + h8 * 8;
            int b = m >> 10, s = m & 1023;
            size_t bhs = ((size_t)(b * NH + head)) * S_ + s;
            if (part == 0) {
                float* base = &g_q[bhs * HD];
#pragma unroll
                for (int nf = 0; nf < 8; nf++) {
                    float2 st = make_float2(c[mf][nf][h8 * 2], c[mf][nf][h8 * 2 + 1]);
                    *(float2*)&base[nf * 8 + (lane & 3) * 2] = st;
                }
            } else if (part == 1) {
                size_t idx = bhs * HD;
#pragma unroll
                for (int nf = 0; nf < 8; nf++) {
                    int d = nf * 8 + (lane & 3) * 2;
                    float x = c[mf][nf][h8 * 2], y = c[mf][nf][h8 * 2 + 1];
                    __nv_bfloat16 hx = __float2bfloat16(x), hy = __float2bfloat16(y);
                    *(uint32_t*)&g_kh[idx + d] = pkbf2(x, y);
                    *(uint32_t*)&g_kl[idx + d] = pkbf2(x - __bfloat162float(hx),
                                                       y - __bfloat162float(hy));
                }
            } else {
                size_t vb = ((size_t)(b * NH + head)) * HD;
#pragma unroll
                for (int nf = 0; nf < 8; nf++) {
                    int d = nf * 8 + (lane & 3) * 2;
#pragma unroll
                    for (int j = 0; j < 2; j++) {
                        float x = c[mf][nf][h8 * 2 + j];
                        __nv_bfloat16 h = __float2bfloat16(x);
                        g_vth[(vb + d + j) * S_ + s] = h;
                        g_vtl[(vb + d + j) * S_ + s] = __float2bfloat16(x - __bfloat162float(h));
                    }
                }
            }
        }
    }
}

// ===========================================================================
// rel bias kernels
// ===========================================================================
__global__ __launch_bounds__(256) void k_relh(const float* __restrict__ RH) {
    const int h = blockIdx.x, bh = blockIdx.y;
    __shared__ float Qs[32][HD + 1], Rs[32][HD + 1];
    const int tid = threadIdx.x;
#pragma unroll
    for (int i = 0; i < 8; i++) {
        int idx = tid + i * 256;
        int r = idx >> 6, c = idx & 63;
        Qs[r][c] = g_q[((size_t)bh * S_ + h * 32 + r) * HD + c];
        Rs[r][c] = RH[(h - r + 31) * HD + c];
    }
    __syncthreads();
    for (int e = tid; e < 1024; e += 256) {
        int w = e >> 5, kh = e & 31;
        float acc = 0.f;
#pragma unroll
        for (int c = 0; c < HD; c++) acc += Qs[w][c] * Rs[kh][c];
        g_relh[((size_t)bh * S_ + h * 32 + w) * 32 + kh] = acc;
    }
}
__global__ __launch_bounds__(256) void k_relw(const float* __restrict__ RW) {
    const int w = blockIdx.x, bh = blockIdx.y;
    __shared__ float Qs[32][HD + 1], Rs[32][HD + 1];
    const int tid = threadIdx.x;
#pragma unroll
    for (int i = 0; i < 8; i++) {
        int idx = tid + i * 256;
        int r = idx >> 6, c = idx & 63;
        Qs[r][c] = g_q[((size_t)bh * S_ + r * 32 + w) * HD + c];
        Rs[r][c] = RW[(w - r + 31) * HD + c];
    }
    __syncthreads();
    for (int e = tid; e < 1024; e += 256) {
        int hh = e >> 5, kw = e & 31;
        float acc = 0.f;
#pragma unroll
        for (int c = 0; c < HD; c++) acc += Qs[hh][c] * Rs[kw][c];
        g_relw[((size_t)bh * S_ + hh * 32 + w) * 32 + kw] = acc;
    }
}

// ===========================================================================
// 2) FLASH: 64-key tiles, cp.async double-buffered K/V (pre-split bf16)
// ===========================================================================
#define QS 72     // Q/K row stride (bf16 elems)
#define VS 72     // V^T row stride
#define BASE2 (2 * 128 * QS)        // after QH/QL
#define STAGE (4 * 64 * QS)         // KH,KL,VH,VL per stage
#define FLASH_SMEM ((BASE2 + 2 * STAGE) * 2)   // 110592 B

__global__ __launch_bounds__(256, 2) void k_flash() {
    extern __shared__ __nv_bfloat16 sm[];
    __nv_bfloat16* QH = sm;
    __nv_bfloat16* QL = sm + 128 * QS;
    const uint32_t sbase = smem_u32(sm);

    const int tid = threadIdx.x, lane = tid & 31, warp = tid >> 5;
    const int bh = blockIdx.y;
    const int rowBlock = blockIdx.x * 128;
    const float* __restrict__ Q = g_q + (size_t)bh * S_ * HD;
    const size_t kbase = (size_t)bh * S_ * HD;
    const size_t vtbase = (size_t)bh * HD * S_;
    const int r0 = lane >> 2;
    const int qBase = rowBlock + warp * 16;

    // async stage fill: 2 chunks per array per thread (64 rows x 8 chunks)
    auto issue = [&](int kt, int st) {
        uint32_t so = sbase + (uint32_t)(BASE2 + st * STAGE) * 2;
#pragma unroll
        for (int i = 0; i < 2; i++) {
            int c16 = tid + i * 256;
            int r = c16 >> 3, off = (c16 & 7) * 8;
            uint32_t dK = so + (uint32_t)(r * QS + off) * 2;
            CP16(dK, g_kh + kbase + (size_t)(kt * 64 + r) * HD + off);
            CP16(dK + 64 * QS * 2, g_kl + kbase + (size_t)(kt * 64 + r) * HD + off);
            uint32_t dV = so + (uint32_t)(2 * 64 * QS + r * VS + off) * 2;
            CP16(dV, g_vth + vtbase + (size_t)r * S_ + kt * 64 + off);
            CP16(dV + 64 * VS * 2, g_vtl + vtbase + (size_t)r * S_ + kt * 64 + off);
        }
        CP_COMMIT();
    };

    issue(0, 0);   // prefetch tile 0 while we convert Q

    // persistent Q tile hi/lo (fp32 -> split, once)
#pragma unroll
    for (int i = 0; i < 8; i++) {
        int f4 = tid + i * 256;
        int r = f4 >> 4, c = (f4 & 15) * 4;
        float4 v = *(const float4*)&Q[(size_t)(rowBlock + r) * HD + c];
        cvtst4(&QH[r * QS + c], &QL[r * QS + c], v);
    }

    // rel_w values (constant across K-tiles)
    float rwv[2][4][2];
#pragma unroll
    for (int h8 = 0; h8 < 2; h8++) {
        int q = qBase + r0 + h8 * 8;
        const float* rw = g_relw + ((size_t)bh * S_ + q) * 32;
#pragma unroll
        for (int t = 0; t < 4; t++) {
            rwv[h8][t][0] = rw[t * 8 + (lane & 3) * 2];
            rwv[h8][t][1] = rw[t * 8 + (lane & 3) * 2 + 1];
        }
    }

    float mcur[2] = {-1e30f, -1e30f};
    float lsum[2] = {0.f, 0.f};
    float o[8][4] = {};

    for (int kt = 0; kt < 16; kt++) {
        const int st = kt & 1;
        if (kt < 15) {
            issue(kt + 1, st ^ 1);
            asm volatile("cp.async.wait_group 1;");
        } else {
            asm volatile("cp.async.wait_group 0;");
        }
        __syncthreads();

        __nv_bfloat16* KHp = sm + BASE2 + st * STAGE;
        __nv_bfloat16* KLp = KHp + 64 * QS;
        __nv_bfloat16* VHp = KHp + 2 * 64 * QS;
        __nv_bfloat16* VLp = VHp + 64 * VS;

        // ---- S = Q K^T over 64 keys ----
        float s[8][4] = {};
#pragma unroll
        for (int kk = 0; kk < 64; kk += 16) {
            uint32_t ah[4], al[4];
            LDSM4(ah, A_ADDRP(QH, QS, warp * 16, kk));
            LDSM4(al, A_ADDRP(QL, QS, warp * 16, kk));
#pragma unroll
            for (int p = 0; p < 4; p++) {
                uint32_t bhf[4], blf[4];
                LDSM4(bhf, B_ADDRP(KHp, QS, p * 16, kk));
                LDSM4(blf, B_ADDRP(KLp, QS, p * 16, kk));
#pragma unroll
                for (int nt = 0; nt < 2; nt++) {
                    float* cc_ = s[p * 2 + nt];
                    mma16816(cc_, ah, bhf + nt * 2);
                    mma16816(cc_, ah, blf + nt * 2);
                    mma16816(cc_, al, bhf + nt * 2);
                }
            }
        }

        // ---- bias + online softmax ----
        float rhv[2][2];
#pragma unroll
        for (int h8 = 0; h8 < 2; h8++) {
            int q = qBase + r0 + h8 * 8;
            const float* rh = g_relh + ((size_t)bh * S_ + q) * 32 + kt * 2;
            rhv[h8][0] = rh[0];
            rhv[h8][1] = rh[1];
        }
        float mnew[2] = {mcur[0], mcur[1]};
#pragma unroll
        for (int nf = 0; nf < 8; nf++)
#pragma unroll
            for (int h8 = 0; h8 < 2; h8++)
#pragma unroll
                for (int j = 0; j < 2; j++) {
                    float val = SCALE * s[nf][h8 * 2 + j] + rhv[h8][nf >> 2] + rwv[h8][nf & 3][j];
                    s[nf][h8 * 2 + j] = val;
                    mnew[h8] = fmaxf(mnew[h8], val);
                }
#pragma unroll
        for (int h8 = 0; h8 < 2; h8++) {
            mnew[h8] = fmaxf(mnew[h8], __shfl_xor_sync(0xffffffffu, mnew[h8], 1));
            mnew[h8] = fmaxf(mnew[h8], __shfl_xor_sync(0xffffffffu, mnew[h8], 2));
        }
        float alpha[2], rs[2] = {0.f, 0.f};
#pragma unroll
        for (int h8 = 0; h8 < 2; h8++) { alpha[h8] = __expf(mcur[h8] - mnew[h8]); mcur[h8] = mnew[h8]; }
#pragma unroll
        for (int nf = 0; nf < 8; nf++)
#pragma unroll
            for (int h8 = 0; h8 < 2; h8++)
#pragma unroll
                for (int j = 0; j < 2; j++) {
                    float p = __expf(s[nf][h8 * 2 + j] - mnew[h8]);
                    s[nf][h8 * 2 + j] = p;
                    rs[h8] += p;
                }
#pragma unroll
        for (int h8 = 0; h8 < 2; h8++) {
            rs[h8] += __shfl_xor_sync(0xffffffffu, rs[h8], 1);
            rs[h8] += __shfl_xor_sync(0xffffffffu, rs[h8], 2);
            lsum[h8] = lsum[h8] * alpha[h8] + rs[h8];
        }
#pragma unroll
        for (int nf = 0; nf < 8; nf++) {
            o[nf][0] *= alpha[0]; o[nf][1] *= alpha[0];
            o[nf][2] *= alpha[1]; o[nf][3] *= alpha[1];
        }

        // ---- O += P @ V ----
#pragma unroll
        for (int ks = 0; ks < 4; ks++) {
            uint32_t aph[4], apl[4];
            float* p0 = s[2 * ks];
            float* p1 = s[2 * ks + 1];
            {
                __nv_bfloat16 h0 = __float2bfloat16(p0[0]), h1 = __float2bfloat16(p0[1]);
                __nv_bfloat16 h2 = __float2bfloat16(p0[2]), h3 = __float2bfloat16(p0[3]);
                aph[0] = pkbf2(p0[0], p0[1]); aph[1] = pkbf2(p0[2], p0[3]);
                apl[0] = pkbf2(p0[0] - __bfloat162float(h0), p0[1] - __bfloat162float(h1));
                apl[1] = pkbf2(p0[2] - __bfloat162float(h2), p0[3] - __bfloat162float(h3));
                __nv_bfloat16 g0 = __float2bfloat16(p1[0]), g1 = __float2bfloat16(p1[1]);
                __nv_bfloat16 g2 = __float2bfloat16(p1[2]), g3 = __float2bfloat16(p1[3]);
                aph[2] = pkbf2(p1[0], p1[1]); aph[3] = pkbf2(p1[2], p1[3]);
                apl[2] = pkbf2(p1[0] - __bfloat162float(g0), p1[1] - __bfloat162float(g1));
                apl[3] = pkbf2(p1[2] - __bfloat162float(g2), p1[3] - __bfloat162float(g3));
            }
#pragma unroll
            for (int dp = 0; dp < 4; dp++) {
                uint32_t vh[4], vl[4];
                LDSM4(vh, B_ADDRP(VHp, VS, dp * 16, ks * 16));
                LDSM4(vl, B_ADDRP(VLp, VS, dp * 16, ks * 16));
#pragma unroll
                for (int nt = 0; nt < 2; nt++) {
                    float* cc_ = o[dp * 2 + nt];
                    mma16816(cc_, aph, vh + nt * 2);
                    mma16816(cc_, aph, vl + nt * 2);
                    mma16816(cc_, apl, vh + nt * 2);
                }
            }
        }
        __syncthreads();   // all reads of this stage done before re-issue
    }

    // epilogue
    float inv[2] = {1.f / lsum[0], 1.f / lsum[1]};
    float* O = g_att + (size_t)bh * S_ * HD;
#pragma unroll
    for (int h8 = 0; h8 < 2; h8++) {
        int q = qBase + r0 + h8 * 8;
#pragma unroll
        for (int nf = 0; nf < 8; nf++) {
            float2 st = make_float2(o[nf][h8 * 2] * inv[h8], o[nf][h8 * 2 + 1] * inv[h8]);
            *(float2*)&O[(size_t)q * HD + nf * 8 + (lane & 3) * 2] = st;
        }
    }
}

// ===========================================================================
// 3) out = gather(att) @ Wproj + bproj
// ===========================================================================
__global__ __launch_bounds__(256) void k_proj(const float* __restrict__ Wp,
                                              const float* __restrict__ bp,
                                              float* __restrict__ out) {
    __shared__ __align__(16) __nv_bfloat16 Ah[128][40], Al[128][40];
    __shared__ __align__(16) __nv_bfloat16 Bh[128][40], Bl[128][40];
    const int tid = threadIdx.x, lane = tid & 31, warp = tid >> 5;
    const int wm = warp & 3, wn = warp >> 2;
    const int rowBlock = blockIdx.y * 128, colBlock = blockIdx.x * 128;
    float c[2][8][4] = {};

    for (int kt = 0; kt < C_; kt += 32) {
#pragma unroll
        for (int i = 0; i < 4; i++) {
            int f4 = tid + i * 256;
            int r = f4 >> 3, cc = (f4 & 7) * 4;
            int row = rowBlock + r;
            int b = row >> 10, s = row & 1023;
            int k = kt + cc;
            int head = k >> 6, d = k & 63;
            float4 v = *(const float4*)&g_att[(((size_t)(b * NH + head)) * S_ + s) * HD + d];
            cvtst4(&Ah[r][cc], &Al[r][cc], v);
        }
#pragma unroll
        for (int i = 0; i < 16; i++) {
            int idx = tid + i * 256;
            int k = idx >> 7, n = idx & 127;
            float v = Wp[(size_t)(kt + k) * C_ + colBlock + n];
            __nv_bfloat16 h = __float2bfloat16(v);
            Bh[n][k] = h;
            Bl[n][k] = __float2bfloat16(v - __bfloat162float(h));
        }
        __syncthreads();
#pragma unroll
        for (int kk = 0; kk < 32; kk += 16) {
            uint32_t ah[2][4], al[2][4];
#pragma unroll
            for (int mf = 0; mf < 2; mf++) {
                LDSM4(ah[mf], A_ADDR(Ah, wm * 32 + mf * 16, kk));
                LDSM4(al[mf], A_ADDR(Al, wm * 32 + mf * 16, kk));
            }
#pragma unroll
            for (int p = 0; p < 4; p++) {
                uint32_t bhf[4], blf[4];
                LDSM4(bhf, B_ADDR(Bh, wn * 64 + p * 16, kk));
                LDSM4(blf, B_ADDR(Bl, wn * 64 + p * 16, kk));
#pragma unroll
                for (int mf = 0; mf < 2; mf++)
#pragma unroll
                    for (int nt = 0; nt < 2; nt++) {
                        float* cc_ = c[mf][p * 2 + nt];
                        mma16816(cc_, ah[mf], bhf + nt * 2);
                        mma16816(cc_, ah[mf], blf + nt * 2);
                        mma16816(cc_, al[mf], bhf + nt * 2);
                    }
            }
        }
        __syncthreads();
    }
    const int col0 = colBlock + wn * 64;
#pragma unroll
    for (int mf = 0; mf < 2; mf++) {
        int m0 = rowBlock + wm * 32 + mf * 16 + (lane >> 2);
#pragma unroll
        for (int h8 = 0; h8 < 2; h8++) {
            int m = m0 + h8 * 8;
#pragma unroll
            for (int nf = 0; nf < 8; nf++) {
                int n = col0 + nf * 8 + (lane & 3) * 2;
                float2 bv = *(const float2*)&bp[n];
                float2 st = make_float2(c[mf][nf][h8 * 2] + bv.x, c[mf][nf][h8 * 2 + 1] + bv.y);
                *(float2*)&out[(size_t)m * C_ + n] = st;
            }
        }
    }
}

// ---------------------------------------------------------------------------
extern "C" void kernel_launch(void* const* d_in, const int* in_sizes, int n_in,
                              void* d_out, int out_size) {
    const float* x     = (const float*)d_in[0];
    const float* Wqkv  = (const float*)d_in[1];
    const float* Wproj = (const float*)d_in[2];
    const float* bproj = (const float*)d_in[3];
    const float* rph   = (const float*)d_in[4];
    const float* rpw   = (const float*)d_in[5];
    float* out = (float*)d_out;

    cudaFuncSetAttribute(k_flash, cudaFuncAttributeMaxDynamicSharedMemorySize, FLASH_SMEM);

    k_qkv<<<dim3(C3 / 128, (B_ * S_) / 128), 256>>>(x, Wqkv);
    k_relh<<<dim3(32, BH), 256>>>(rph);
    k_relw<<<dim3(32, BH), 256>>>(rpw);
    k_flash<<<dim3(S_ / 128, BH), 256, FLASH_SMEM>>>();
    k_proj<<<dim3(C_ / 128, (B_ * S_) / 128), 256>>>(Wproj, bproj, out);
}